// round 10
// baseline (speedup 1.0000x reference)
#include <cuda_runtime.h>
#include <cuda_fp16.h>
#include <stdint.h>
#include <math.h>

#define D_MODEL 1024
#define HEADS 16
#define DK 64
#define BATCH 2
#define SEQ 2048
#define M_ROWS (BATCH * SEQ)   // 4096
#define BH (BATCH * HEADS)     // 32

typedef __half fp16;

// ---------------- scratch (static device globals; no allocation) -------------
__device__ fp16 g_ahi[(size_t)3 * M_ROWS * D_MODEL];   // activation sets (hi)
__device__ fp16 g_alo[(size_t)3 * M_ROWS * D_MODEL];   // activation sets (lo)
__device__ fp16 g_whi[(size_t)4 * D_MODEL * D_MODEL];  // W^T hi only [N][K]
__device__ fp16 g_qhi[(size_t)BH * SEQ * DK];          // [bh][s][d], pre-scaled 0.125
__device__ fp16 g_qlo[(size_t)BH * SEQ * DK];
__device__ fp16 g_khi[(size_t)BH * SEQ * DK];          // hi only
__device__ fp16 g_vhi[(size_t)BH * DK * SEQ];          // transposed [bh][d][s], hi only

// ---------------------------------------------------------------------------
// MMA building blocks (mma.sync path — tcgen05 unavailable: harness PTX
// targets sm_103 without the 'a' feature suffix). fp16 inputs, fp32 accum.
// ---------------------------------------------------------------------------
#define LDSM4(R0, R1, R2, R3, ADDR) \
    asm volatile("ldmatrix.sync.aligned.m8n8.x4.shared.b16 {%0,%1,%2,%3}, [%4];" \
        : "=r"(R0), "=r"(R1), "=r"(R2), "=r"(R3) : "r"(ADDR))

#define MMA_F16(D, A, B) \
    asm volatile("mma.sync.aligned.m16n8k16.row.col.f32.f16.f16.f32 " \
        "{%0,%1,%2,%3}, {%4,%5,%6,%7}, {%8,%9}, {%0,%1,%2,%3};" \
        : "+f"(D[0]), "+f"(D[1]), "+f"(D[2]), "+f"(D[3]) \
        : "r"(A[0]), "r"(A[1]), "r"(A[2]), "r"(A[3]), "r"(B[0]), "r"(B[1]))

#define CP16(DST, SRC) \
    asm volatile("cp.async.cg.shared.global [%0], [%1], 16;" :: "r"(DST), "l"(SRC))

// ---------------------------------------------------------------------------
// merged converts (grid.z selects tensor)
// ---------------------------------------------------------------------------
struct ConvA { const float* in[3]; fp16* hi[3]; fp16* lo[3]; };

__global__ void __launch_bounds__(256) convert_act_kernel(ConvA a)
{
    const int z = blockIdx.z;
    const float* in = a.in[z];
    fp16* hi = a.hi[z];
    fp16* lo = a.lo[z];
    const int base = blockIdx.x * 1024 + threadIdx.x;
#pragma unroll
    for (int jj = 0; jj < 4; jj++) {
        int i = base + jj * 256;
        float4 v = ((const float4*)in)[i];
        float f[4] = {v.x, v.y, v.z, v.w};
        union { fp16 h[4]; uint2 u; } uh, ul;
#pragma unroll
        for (int j = 0; j < 4; j++) {
            uh.h[j] = __float2half_rn(f[j]);
            ul.h[j] = __float2half_rn(f[j] - __half2float(uh.h[j]));
        }
        ((uint2*)hi)[i] = uh.u;
        ((uint2*)lo)[i] = ul.u;
    }
}

struct ConvW { const float* W[4]; fp16* hi[4]; };

__global__ void convert_wT_kernel(ConvW a)
{
    __shared__ float t[32][33];
    const int z = blockIdx.z;
    const float* W = a.W[z];
    fp16* hiT = a.hi[z];
    const int k0 = blockIdx.x * 32, n0 = blockIdx.y * 32;
    const int tx = threadIdx.x, ty = threadIdx.y;
#pragma unroll
    for (int j = 0; j < 4; j++)
        t[ty + j * 8][tx] = W[(size_t)(k0 + ty + j * 8) * D_MODEL + n0 + tx];
    __syncthreads();
#pragma unroll
    for (int j = 0; j < 4; j++) {
        float v = t[tx][ty + j * 8];
        hiT[(size_t)(n0 + ty + j * 8) * D_MODEL + k0 + tx] = __float2half_rn(v);
    }
}

// ---------------------------------------------------------------------------
// GEMM via mma.sync fp16 (2-term split): C = A*W^T + bias
// Terms: Ah*Bh + Al*Bh  (B lo not needed at fp16 precision).
// mode 0: fp32 C row-major. 1: fp16 head-split hi (+lo if Clo). 2: transposed V hi.
// ---------------------------------------------------------------------------
#define BM 128
#define BN 128
#define BK 32
#define SK 40
#define MAT_ELEMS (128 * SK)
#define STAGE_ELEMS (3 * MAT_ELEMS)

struct GemmJob {
    const fp16 *Ah, *Al, *Bh;
    const float* bias;
    float* Cf;
    fp16 *Chi, *Clo;
    int mode;
    float oscale;
};

__global__ void __launch_bounds__(256, 2) gemm_mma_kernel(GemmJob jb)
{
    extern __shared__ __align__(16) fp16 sm[];
    const fp16* __restrict__ Ahi = jb.Ah;
    const fp16* __restrict__ Alo = jb.Al;
    const fp16* __restrict__ Bhi = jb.Bh;
    const float* __restrict__ bias = jb.bias;

    const int tid = threadIdx.x;
    const int lane = tid & 31, warp = tid >> 5;
    const int wm = warp >> 2, wn = warp & 3;
    const int m0 = blockIdx.y * BM, n0 = blockIdx.x * BN;

    const int r0 = tid >> 2;
    const int cc0 = (tid & 3) * 8;

    uint32_t s_base[2];
    s_base[0] = (uint32_t)__cvta_generic_to_shared(sm);
    s_base[1] = s_base[0] + STAGE_ELEMS * 2;

    const uint32_t gA0 = (uint32_t)(m0 + r0) * D_MODEL + cc0;
    const uint32_t gA1 = (uint32_t)(m0 + r0 + 64) * D_MODEL + cc0;
    const uint32_t gB0 = (uint32_t)(n0 + r0) * D_MODEL + cc0;
    const uint32_t gB1 = (uint32_t)(n0 + r0 + 64) * D_MODEL + cc0;
    const uint32_t sOff0 = (uint32_t)(r0 * SK + cc0) * 2;
    const uint32_t sOff1 = (uint32_t)((r0 + 64) * SK + cc0) * 2;

    float acc[4][4][4];
#pragma unroll
    for (int a = 0; a < 4; a++)
#pragma unroll
        for (int b = 0; b < 4; b++)
#pragma unroll
            for (int c = 0; c < 4; c++) acc[a][b][c] = 0.f;

    const uint32_t aRow = wm * 64 + (lane & 15);
    const uint32_t aCol = (lane >> 4) * 8;
    const uint32_t bRow = wn * 32 + (lane & 7) + ((lane >> 4) & 1) * 8;
    const uint32_t bCol = ((lane >> 3) & 1) * 8;

#define LOAD_STAGE(S, K0) do { \
    uint32_t sb = s_base[(S) & 1]; \
    CP16(sb + sOff0,                     Ahi + gA0 + (K0)); \
    CP16(sb + sOff1,                     Ahi + gA1 + (K0)); \
    CP16(sb + MAT_ELEMS * 2 + sOff0,     Alo + gA0 + (K0)); \
    CP16(sb + MAT_ELEMS * 2 + sOff1,     Alo + gA1 + (K0)); \
    CP16(sb + 2 * MAT_ELEMS * 2 + sOff0, Bhi + gB0 + (K0)); \
    CP16(sb + 2 * MAT_ELEMS * 2 + sOff1, Bhi + gB1 + (K0)); \
    asm volatile("cp.async.commit_group;"); \
} while (0)

    LOAD_STAGE(0, 0);

    const int NSTAGE = D_MODEL / BK;
    for (int s = 0; s < NSTAGE; ++s) {
        asm volatile("cp.async.wait_group 0;" ::: "memory");
        __syncthreads();
        if (s + 1 < NSTAGE) LOAD_STAGE(s + 1, (uint32_t)(s + 1) * BK);

        const uint32_t sb = s_base[s & 1];
        const uint32_t aBaseH = sb + (aRow * SK + aCol) * 2;
        const uint32_t aBaseL = aBaseH + MAT_ELEMS * 2;
        const uint32_t bBaseH = sb + 2 * MAT_ELEMS * 2 + (bRow * SK + bCol) * 2;

#pragma unroll
        for (int ks = 0; ks < 2; ++ks) {
            uint32_t ah[4][4], al[4][4], bh[4][2];
#pragma unroll
            for (int mf = 0; mf < 4; ++mf) {
                uint32_t off = (uint32_t)(mf * 16 * SK + ks * 16) * 2;
                LDSM4(ah[mf][0], ah[mf][1], ah[mf][2], ah[mf][3], aBaseH + off);
                LDSM4(al[mf][0], al[mf][1], al[mf][2], al[mf][3], aBaseL + off);
            }
#pragma unroll
            for (int p = 0; p < 2; ++p) {
                uint32_t off = (uint32_t)(p * 16 * SK + ks * 16) * 2;
                LDSM4(bh[2 * p][0], bh[2 * p][1], bh[2 * p + 1][0], bh[2 * p + 1][1], bBaseH + off);
            }
#pragma unroll
            for (int mf = 0; mf < 4; ++mf)
#pragma unroll
                for (int nf = 0; nf < 4; ++nf)
                    MMA_F16(acc[mf][nf], ah[mf], bh[nf]);
#pragma unroll
            for (int mf = 0; mf < 4; ++mf)
#pragma unroll
                for (int nf = 0; nf < 4; ++nf)
                    MMA_F16(acc[mf][nf], al[mf], bh[nf]);
        }
    }

    const int l4 = lane >> 2, l2 = (lane & 3) * 2;
#pragma unroll
    for (int mf = 0; mf < 4; ++mf) {
#pragma unroll
        for (int nf = 0; nf < 4; ++nf) {
            const int r = m0 + wm * 64 + mf * 16 + l4;
            const int c = n0 + wn * 32 + nf * 8 + l2;
            const float bx = bias[c], by = bias[c + 1];
            float v00 = acc[mf][nf][0] + bx, v01 = acc[mf][nf][1] + by;
            float v10 = acc[mf][nf][2] + bx, v11 = acc[mf][nf][3] + by;
            if (jb.mode == 0) {
                *(float2*)&jb.Cf[(size_t)r * D_MODEL + c] = make_float2(v00, v01);
                *(float2*)&jb.Cf[(size_t)(r + 8) * D_MODEL + c] = make_float2(v10, v11);
            } else {
                v00 *= jb.oscale; v01 *= jb.oscale; v10 *= jb.oscale; v11 *= jb.oscale;
                const int b = r >> 11, sx = r & (SEQ - 1);
                const int h = c >> 6, d = c & (DK - 1);
                const int bhh = b * HEADS + h;
                if (jb.mode == 1) {
                    __half2 h0 = __floats2half2_rn(v00, v01);
                    __half2 h1 = __floats2half2_rn(v10, v11);
                    size_t o0 = ((size_t)bhh * SEQ + sx) * DK + d;
                    size_t o1 = ((size_t)bhh * SEQ + sx + 8) * DK + d;
                    *(__half2*)&jb.Chi[o0] = h0;
                    *(__half2*)&jb.Chi[o1] = h1;
                    if (jb.Clo) {
                        __half2 L0 = __floats2half2_rn(v00 - __low2float(h0), v01 - __high2float(h0));
                        __half2 L1 = __floats2half2_rn(v10 - __low2float(h1), v11 - __high2float(h1));
                        *(__half2*)&jb.Clo[o0] = L0;
                        *(__half2*)&jb.Clo[o1] = L1;
                    }
                } else {  // mode 2: transposed [bh][d][s], hi only
                    size_t base = (size_t)bhh * DK * SEQ;
                    float vv[4] = {v00, v01, v10, v11};
                    int dd[4] = {d, d + 1, d, d + 1};
                    int ss[4] = {sx, sx, sx + 8, sx + 8};
#pragma unroll
                    for (int e = 0; e < 4; e++)
                        jb.Chi[base + (size_t)dd[e] * SEQ + ss[e]] = __float2half_rn(vv[e]);
                }
            }
        }
    }
}

// ---------------------------------------------------------------------------
// fast exp on the FMA pipe
// ---------------------------------------------------------------------------
__device__ __forceinline__ float exp_fast(float x)
{
    float y = fmaxf(x * 1.4426950408889634f, -120.f);
    float jf = y + 12582912.f;
    float jr = jf - 12582912.f;
    float t = (y - jr) * 0.6931471805599453f;
    float p = fmaf(t, 0.008333333f, 0.041666668f);
    p = fmaf(t, p, 0.16666667f);
    p = fmaf(t, p, 0.5f);
    p = fmaf(t, p, 1.0f);
    p = fmaf(t, p, 1.0f);
    int e = (__float_as_int(jf) - 0x4B400000 + 127) << 23;
    return p * __int_as_float(e);
}

// ---------------------------------------------------------------------------
// Flash attention (causal), mma.sync fp16 2-term split (K/V hi only).
// Stage = Kh + Vh tiles (18432 B each pair = 36864 B); 2 stages = 73728 B.
// launch_bounds(128, 4): 4 CTAs/SM (reg-capped at 128), 16 warps/SM.
// ---------------------------------------------------------------------------
#define FSK 72
#define FTILE (64 * FSK)
#define FSTAGE (2 * FTILE)

__global__ void __launch_bounds__(128, 4) flash_mma_kernel(
    const fp16* __restrict__ Qh, const fp16* __restrict__ Ql,
    const fp16* __restrict__ Kh, const fp16* __restrict__ Vh,
    fp16* __restrict__ Ohi, fp16* __restrict__ Olo)
{
    extern __shared__ __align__(16) fp16 fsm[];
    const int tid = threadIdx.x, lane = tid & 31, w = tid >> 5;
    const int qt = gridDim.x - 1 - blockIdx.x, bh = blockIdx.y;

    const uint32_t sb = (uint32_t)__cvta_generic_to_shared(fsm);
    const uint32_t sQh = sb + FSTAGE * 2;               // Q staged in buffer 1
    const uint32_t sQl = sQh + FTILE * 2;

    const size_t gQ = ((size_t)bh * SEQ + (size_t)qt * 64) * DK;
    const size_t gK = (size_t)bh * SEQ * DK;
    const size_t gV = (size_t)bh * DK * SEQ;

#define FLOADQ() do { \
    _Pragma("unroll") \
    for (int i = 0; i < 4; i++) { \
        int idx = tid + i * 128; int rr = idx >> 3; int cc = (idx & 7) * 8; \
        uint32_t so = (uint32_t)(rr * FSK + cc) * 2; \
        CP16(sQh + so, Qh + gQ + rr * DK + cc); \
        CP16(sQl + so, Ql + gQ + rr * DK + cc); \
    } \
} while (0)

#define FLOADKV(S, KT) do { \
    uint32_t st = sb + (uint32_t)(S) * FSTAGE * 2; \
    _Pragma("unroll") \
    for (int i = 0; i < 4; i++) { \
        int idx = tid + i * 128; int rr = idx >> 3; int cc = (idx & 7) * 8; \
        uint32_t so = (uint32_t)(rr * FSK + cc) * 2; \
        CP16(st + so,             Kh + gK + (size_t)((KT) * 64 + rr) * DK + cc); \
        CP16(st + FTILE * 2 + so, Vh + gV + (size_t)rr * SEQ + (KT) * 64 + cc); \
    } \
    asm volatile("cp.async.commit_group;"); \
} while (0)

    FLOADQ();          // into buffer 1 (committed with the group below)
    FLOADKV(0, 0);     // into buffer 0

    const uint32_t aOff = (uint32_t)((w * 16 + (lane & 15)) * FSK + (lane >> 4) * 8) * 2;
    const uint32_t bRowOff = (lane & 7) + ((lane >> 4) & 1) * 8;
    const uint32_t bColOff = ((lane >> 3) & 1) * 8;

    const int l4 = lane >> 2, l2 = (lane & 3) * 2;
    const int rowBaseA = w * 16 + l4;
    float m0 = -3.0e38f, m1 = -3.0e38f, l0 = 0.f, l1 = 0.f;
    float o[8][4];
#pragma unroll
    for (int n = 0; n < 8; n++)
#pragma unroll
        for (int c = 0; c < 4; c++) o[n][c] = 0.f;

    uint32_t qhf[4][4], qlf[4][4];

    for (int kt = 0; kt <= qt; ++kt) {
        asm volatile("cp.async.wait_group 0;" ::: "memory");
        __syncthreads();

        if (kt == 0) {
            // consume Q from buffer 1 into registers, then free it for prefetch
#pragma unroll
            for (int kk = 0; kk < 4; ++kk) {
                uint32_t off = aOff + (uint32_t)(kk * 16) * 2;
                LDSM4(qhf[kk][0], qhf[kk][1], qhf[kk][2], qhf[kk][3], sQh + off);
                LDSM4(qlf[kk][0], qlf[kk][1], qlf[kk][2], qlf[kk][3], sQl + off);
            }
            __syncthreads();   // all warps done reading Q before overwrite
            if (kt < qt) FLOADKV(1, 1);
        } else {
            if (kt < qt) FLOADKV((kt + 1) & 1, kt + 1);
        }

        const uint32_t stg = sb + (uint32_t)(kt & 1) * FSTAGE * 2;

        float s[8][4];
#pragma unroll
        for (int n = 0; n < 8; n++)
#pragma unroll
            for (int c = 0; c < 4; c++) s[n][c] = 0.f;

#pragma unroll
        for (int kk = 0; kk < 4; ++kk) {
            uint32_t khf[8][2];
#pragma unroll
            for (int p = 0; p < 4; ++p) {
                uint32_t off = (uint32_t)((p * 16 + bRowOff) * FSK + bColOff + kk * 16) * 2;
                LDSM4(khf[2 * p][0], khf[2 * p][1], khf[2 * p + 1][0], khf[2 * p + 1][1], stg + off);
            }
#pragma unroll
            for (int n = 0; n < 8; n++)
                MMA_F16(s[n], qhf[kk], khf[n]);
#pragma unroll
            for (int n = 0; n < 8; n++)
                MMA_F16(s[n], qlf[kk], khf[n]);
        }

        float r0 = -3.0e38f, r1 = -3.0e38f;
#pragma unroll
        for (int n = 0; n < 8; n++) {
            r0 = fmaxf(r0, fmaxf(s[n][0], s[n][1]));
            r1 = fmaxf(r1, fmaxf(s[n][2], s[n][3]));
        }
        r0 = fmaxf(r0, __shfl_xor_sync(0xffffffffu, r0, 1));
        r0 = fmaxf(r0, __shfl_xor_sync(0xffffffffu, r0, 2));
        r1 = fmaxf(r1, __shfl_xor_sync(0xffffffffu, r1, 1));
        r1 = fmaxf(r1, __shfl_xor_sync(0xffffffffu, r1, 2));
        float mn0 = fmaxf(m0, r0), mn1 = fmaxf(m1, r1);
        float corr0 = exp_fast(m0 - mn0), corr1 = exp_fast(m1 - mn1);
        m0 = mn0; m1 = mn1;

        const bool diag = (kt == qt);
        float ls0 = 0.f, ls1 = 0.f;
#pragma unroll
        for (int n = 0; n < 8; n++) {
            float p0 = exp_fast(s[n][0] - mn0);
            float p1 = exp_fast(s[n][1] - mn0);
            float p2 = exp_fast(s[n][2] - mn1);
            float p3 = exp_fast(s[n][3] - mn1);
            if (diag) {
                int cb = n * 8 + l2;
                if (cb > rowBaseA) p0 = 0.f;
                if (cb + 1 > rowBaseA) p1 = 0.f;
                if (cb > rowBaseA + 8) p2 = 0.f;
                if (cb + 1 > rowBaseA + 8) p3 = 0.f;
            }
            s[n][0] = p0; s[n][1] = p1; s[n][2] = p2; s[n][3] = p3;
            ls0 += p0 + p1; ls1 += p2 + p3;
        }
        l0 = l0 * corr0 + ls0;
        l1 = l1 * corr1 + ls1;
#pragma unroll
        for (int n = 0; n < 8; n++) {
            o[n][0] *= corr0; o[n][1] *= corr0;
            o[n][2] *= corr1; o[n][3] *= corr1;
        }

        // pack P to fp16 hi/lo A-fragments (in-register)
        uint32_t aPh[4][4], aPl[4][4];
#pragma unroll
        for (int kk = 0; kk < 4; ++kk) {
            const int n0i = 2 * kk, n1i = 2 * kk + 1;
            __half2 h;
            h = __floats2half2_rn(s[n0i][0], s[n0i][1]);
            aPh[kk][0] = *(uint32_t*)&h;
            {   __half2 L = __floats2half2_rn(s[n0i][0] - __low2float(h), s[n0i][1] - __high2float(h));
                aPl[kk][0] = *(uint32_t*)&L; }
            h = __floats2half2_rn(s[n0i][2], s[n0i][3]);
            aPh[kk][1] = *(uint32_t*)&h;
            {   __half2 L = __floats2half2_rn(s[n0i][2] - __low2float(h), s[n0i][3] - __high2float(h));
                aPl[kk][1] = *(uint32_t*)&L; }
            h = __floats2half2_rn(s[n1i][0], s[n1i][1]);
            aPh[kk][2] = *(uint32_t*)&h;
            {   __half2 L = __floats2half2_rn(s[n1i][0] - __low2float(h), s[n1i][1] - __high2float(h));
                aPl[kk][2] = *(uint32_t*)&L; }
            h = __floats2half2_rn(s[n1i][2], s[n1i][3]);
            aPh[kk][3] = *(uint32_t*)&h;
            {   __half2 L = __floats2half2_rn(s[n1i][2] - __low2float(h), s[n1i][3] - __high2float(h));
                aPl[kk][3] = *(uint32_t*)&L; }
        }

#pragma unroll
        for (int kk = 0; kk < 4; ++kk) {
            uint32_t vhf[8][2];
#pragma unroll
            for (int p = 0; p < 4; ++p) {
                uint32_t off = (uint32_t)((p * 16 + bRowOff) * FSK + bColOff + kk * 16) * 2;
                LDSM4(vhf[2 * p][0], vhf[2 * p][1], vhf[2 * p + 1][0], vhf[2 * p + 1][1],
                      stg + FTILE * 2 + off);
            }
#pragma unroll
            for (int n = 0; n < 8; n++)
                MMA_F16(o[n], aPh[kk], vhf[n]);
#pragma unroll
            for (int n = 0; n < 8; n++)
                MMA_F16(o[n], aPl[kk], vhf[n]);
        }
    }

    l0 += __shfl_xor_sync(0xffffffffu, l0, 1);
    l0 += __shfl_xor_sync(0xffffffffu, l0, 2);
    l1 += __shfl_xor_sync(0xffffffffu, l1, 1);
    l1 += __shfl_xor_sync(0xffffffffu, l1, 2);
    const float inv0 = 1.f / l0, inv1 = 1.f / l1;

    const int b = bh >> 4, hh = bh & 15;
    const int grow = qt * 64 + rowBaseA;
    const size_t rbase0 = ((size_t)b * SEQ + grow) * D_MODEL + hh * DK;
    const size_t rbase1 = rbase0 + (size_t)8 * D_MODEL;
#pragma unroll
    for (int n = 0; n < 8; n++) {
        const int d = n * 8 + l2;
        float v0 = o[n][0] * inv0, v1 = o[n][1] * inv0;
        float v2 = o[n][2] * inv1, v3 = o[n][3] * inv1;
        __half2 h0 = __floats2half2_rn(v0, v1);
        __half2 h1 = __floats2half2_rn(v2, v3);
        __half2 L0 = __floats2half2_rn(v0 - __low2float(h0), v1 - __high2float(h0));
        __half2 L1 = __floats2half2_rn(v2 - __low2float(h1), v3 - __high2float(h1));
        *(__half2*)&Ohi[rbase0 + d] = h0;
        *(__half2*)&Olo[rbase0 + d] = L0;
        *(__half2*)&Ohi[rbase1 + d] = h1;
        *(__half2*)&Olo[rbase1 + d] = L1;
    }
}

// ---------------------------------------------------------------------------
extern "C" void kernel_launch(void* const* d_in, const int* in_sizes, int n_in,
                              void* d_out, int out_size)
{
    const float* query = (const float*)d_in[0];
    const float* key   = (const float*)d_in[1];
    const float* value = (const float*)d_in[2];
    // d_in[3] = mask (causal handled analytically)
    const float* Wq = (const float*)d_in[4];
    const float* bq = (const float*)d_in[5];
    const float* Wk = (const float*)d_in[6];
    const float* bk = (const float*)d_in[7];
    const float* Wv = (const float*)d_in[8];
    const float* bv = (const float*)d_in[9];
    const float* Wo = (const float*)d_in[10];
    const float* bo = (const float*)d_in[11];
    float* out = (float*)d_out;

    fp16 *ahi, *alo, *whi, *qhi, *qlo, *khi, *vhi;
    cudaGetSymbolAddress((void**)&ahi, g_ahi);
    cudaGetSymbolAddress((void**)&alo, g_alo);
    cudaGetSymbolAddress((void**)&whi, g_whi);
    cudaGetSymbolAddress((void**)&qhi, g_qhi);
    cudaGetSymbolAddress((void**)&qlo, g_qlo);
    cudaGetSymbolAddress((void**)&khi, g_khi);
    cudaGetSymbolAddress((void**)&vhi, g_vhi);

    const size_t ASTRIDE = (size_t)M_ROWS * D_MODEL;
    const size_t WSTRIDE = (size_t)D_MODEL * D_MODEL;

    const int gemm_smem = STAGE_ELEMS * 2 * 2;     // 61440 B (x2 CTAs = 123KB/SM)
    cudaFuncSetAttribute(gemm_mma_kernel,
                         cudaFuncAttributeMaxDynamicSharedMemorySize, gemm_smem);
    const int flash_smem = 2 * FSTAGE * 2;         // 36864 B (x4 CTAs = 147KB/SM)
    cudaFuncSetAttribute(flash_mma_kernel,
                         cudaFuncAttributeMaxDynamicSharedMemorySize, flash_smem);

    // 1. convert activations — one merged launch (grid.z = 3), 4 float4/thread
    ConvA ca;
    ca.in[0] = query; ca.in[1] = key; ca.in[2] = value;
    for (int i = 0; i < 3; i++) { ca.hi[i] = ahi + i * ASTRIDE; ca.lo[i] = alo + i * ASTRIDE; }
    convert_act_kernel<<<dim3(M_ROWS * D_MODEL / 4096, 1, 3), 256>>>(ca);

    // 2. convert + transpose weights (hi only) — one merged launch (grid.z = 4)
    ConvW cw;
    cw.W[0] = Wq; cw.W[1] = Wk; cw.W[2] = Wv; cw.W[3] = Wo;
    for (int i = 0; i < 4; i++) cw.hi[i] = whi + i * WSTRIDE;
    convert_wT_kernel<<<dim3(32, 32, 4), dim3(32, 8)>>>(cw);

    // 3-5. QKV projections
    dim3 gg(D_MODEL / BN, M_ROWS / BM);
    GemmJob jq = { ahi + 0 * ASTRIDE, alo + 0 * ASTRIDE, whi + 0 * WSTRIDE,
                   bq, nullptr, qhi, qlo, 1, 0.125f };
    gemm_mma_kernel<<<gg, 256, gemm_smem>>>(jq);
    GemmJob jk = { ahi + 1 * ASTRIDE, alo + 1 * ASTRIDE, whi + 1 * WSTRIDE,
                   bk, nullptr, khi, nullptr, 1, 1.0f };
    gemm_mma_kernel<<<gg, 256, gemm_smem>>>(jk);
    GemmJob jv = { ahi + 2 * ASTRIDE, alo + 2 * ASTRIDE, whi + 2 * WSTRIDE,
                   bv, nullptr, vhi, nullptr, 2, 1.0f };
    gemm_mma_kernel<<<gg, 256, gemm_smem>>>(jv);

    // 6. flash attention — writes O as fp16 hi/lo into activation set 0
    flash_mma_kernel<<<dim3(SEQ / 64, BH), 128, flash_smem>>>(
        qhi, qlo, khi, vhi, ahi, alo);

    // 7. output projection — fp32 out
    GemmJob jo = { ahi, alo, whi + 3 * WSTRIDE,
                   bo, out, nullptr, nullptr, 0, 1.0f };
    gemm_mma_kernel<<<gg, 256, gemm_smem>>>(jo);
}

// round 12
// speedup vs baseline: 1.0883x; 1.0883x over previous
#include <cuda_runtime.h>
#include <cuda_fp16.h>
#include <stdint.h>
#include <math.h>

#define D_MODEL 1024
#define HEADS 16
#define DK 64
#define BATCH 2
#define SEQ 2048
#define M_ROWS (BATCH * SEQ)   // 4096
#define BH (BATCH * HEADS)     // 32
#define LOG2E 1.4426950408889634f

typedef __half fp16;

// ---------------- scratch (static device globals; no allocation) -------------
__device__ fp16 g_ahi[(size_t)3 * M_ROWS * D_MODEL];   // activation sets (hi)
__device__ fp16 g_alo[(size_t)3 * M_ROWS * D_MODEL];   // activation sets (lo)
__device__ fp16 g_whi[(size_t)4 * D_MODEL * D_MODEL];  // W^T hi only [N][K]
__device__ fp16 g_qhi[(size_t)BH * SEQ * DK];          // [bh][s][d], pre-scaled 0.125
__device__ fp16 g_qlo[(size_t)BH * SEQ * DK];
__device__ fp16 g_khi[(size_t)BH * SEQ * DK];          // hi only
__device__ fp16 g_vhi[(size_t)BH * DK * SEQ];          // transposed [bh][d][s], hi only

// ---------------------------------------------------------------------------
// MMA building blocks (mma.sync path — tcgen05 unavailable: harness PTX
// targets sm_103 without the 'a' feature suffix). fp16 inputs, fp32 accum.
// ---------------------------------------------------------------------------
#define LDSM4(R0, R1, R2, R3, ADDR) \
    asm volatile("ldmatrix.sync.aligned.m8n8.x4.shared.b16 {%0,%1,%2,%3}, [%4];" \
        : "=r"(R0), "=r"(R1), "=r"(R2), "=r"(R3) : "r"(ADDR))

#define MMA_F16(D, A, B) \
    asm volatile("mma.sync.aligned.m16n8k16.row.col.f32.f16.f16.f32 " \
        "{%0,%1,%2,%3}, {%4,%5,%6,%7}, {%8,%9}, {%0,%1,%2,%3};" \
        : "+f"(D[0]), "+f"(D[1]), "+f"(D[2]), "+f"(D[3]) \
        : "r"(A[0]), "r"(A[1]), "r"(A[2]), "r"(A[3]), "r"(B[0]), "r"(B[1]))

#define CP16(DST, SRC) \
    asm volatile("cp.async.cg.shared.global [%0], [%1], 16;" :: "r"(DST), "l"(SRC))

// ---------------------------------------------------------------------------
// merged converts (grid.z selects tensor)
// ---------------------------------------------------------------------------
struct ConvA { const float* in[3]; fp16* hi[3]; fp16* lo[3]; };

__global__ void __launch_bounds__(256) convert_act_kernel(ConvA a)
{
    const int z = blockIdx.z;
    const float* in = a.in[z];
    fp16* hi = a.hi[z];
    fp16* lo = a.lo[z];
    const int base = blockIdx.x * 1024 + threadIdx.x;
#pragma unroll
    for (int jj = 0; jj < 4; jj++) {
        int i = base + jj * 256;
        float4 v = ((const float4*)in)[i];
        float f[4] = {v.x, v.y, v.z, v.w};
        union { fp16 h[4]; uint2 u; } uh, ul;
#pragma unroll
        for (int j = 0; j < 4; j++) {
            uh.h[j] = __float2half_rn(f[j]);
            ul.h[j] = __float2half_rn(f[j] - __half2float(uh.h[j]));
        }
        ((uint2*)hi)[i] = uh.u;
        ((uint2*)lo)[i] = ul.u;
    }
}

struct ConvW { const float* W[4]; fp16* hi[4]; };

__global__ void convert_wT_kernel(ConvW a)
{
    __shared__ float t[32][33];
    const int z = blockIdx.z;
    const float* W = a.W[z];
    fp16* hiT = a.hi[z];
    const int k0 = blockIdx.x * 32, n0 = blockIdx.y * 32;
    const int tx = threadIdx.x, ty = threadIdx.y;
#pragma unroll
    for (int j = 0; j < 4; j++)
        t[ty + j * 8][tx] = W[(size_t)(k0 + ty + j * 8) * D_MODEL + n0 + tx];
    __syncthreads();
#pragma unroll
    for (int j = 0; j < 4; j++) {
        float v = t[tx][ty + j * 8];
        hiT[(size_t)(n0 + ty + j * 8) * D_MODEL + k0 + tx] = __float2half_rn(v);
    }
}

// ---------------------------------------------------------------------------
// GEMM via mma.sync fp16 (2-term split): C = A*W^T + bias — unchanged R10.
// ---------------------------------------------------------------------------
#define BM 128
#define BN 128
#define BK 32
#define SK 40
#define MAT_ELEMS (128 * SK)
#define STAGE_ELEMS (3 * MAT_ELEMS)

struct GemmJob {
    const fp16 *Ah, *Al, *Bh;
    const float* bias;
    float* Cf;
    fp16 *Chi, *Clo;
    int mode;
    float oscale;
};

__global__ void __launch_bounds__(256, 2) gemm_mma_kernel(GemmJob jb)
{
    extern __shared__ __align__(16) fp16 sm[];
    const fp16* __restrict__ Ahi = jb.Ah;
    const fp16* __restrict__ Alo = jb.Al;
    const fp16* __restrict__ Bhi = jb.Bh;
    const float* __restrict__ bias = jb.bias;

    const int tid = threadIdx.x;
    const int lane = tid & 31, warp = tid >> 5;
    const int wm = warp >> 2, wn = warp & 3;
    const int m0 = blockIdx.y * BM, n0 = blockIdx.x * BN;

    const int r0 = tid >> 2;
    const int cc0 = (tid & 3) * 8;

    uint32_t s_base[2];
    s_base[0] = (uint32_t)__cvta_generic_to_shared(sm);
    s_base[1] = s_base[0] + STAGE_ELEMS * 2;

    const uint32_t gA0 = (uint32_t)(m0 + r0) * D_MODEL + cc0;
    const uint32_t gA1 = (uint32_t)(m0 + r0 + 64) * D_MODEL + cc0;
    const uint32_t gB0 = (uint32_t)(n0 + r0) * D_MODEL + cc0;
    const uint32_t gB1 = (uint32_t)(n0 + r0 + 64) * D_MODEL + cc0;
    const uint32_t sOff0 = (uint32_t)(r0 * SK + cc0) * 2;
    const uint32_t sOff1 = (uint32_t)((r0 + 64) * SK + cc0) * 2;

    float acc[4][4][4];
#pragma unroll
    for (int a = 0; a < 4; a++)
#pragma unroll
        for (int b = 0; b < 4; b++)
#pragma unroll
            for (int c = 0; c < 4; c++) acc[a][b][c] = 0.f;

    const uint32_t aRow = wm * 64 + (lane & 15);
    const uint32_t aCol = (lane >> 4) * 8;
    const uint32_t bRow = wn * 32 + (lane & 7) + ((lane >> 4) & 1) * 8;
    const uint32_t bCol = ((lane >> 3) & 1) * 8;

#define LOAD_STAGE(S, K0) do { \
    uint32_t sb = s_base[(S) & 1]; \
    CP16(sb + sOff0,                     Ahi + gA0 + (K0)); \
    CP16(sb + sOff1,                     Ahi + gA1 + (K0)); \
    CP16(sb + MAT_ELEMS * 2 + sOff0,     Alo + gA0 + (K0)); \
    CP16(sb + MAT_ELEMS * 2 + sOff1,     Alo + gA1 + (K0)); \
    CP16(sb + 2 * MAT_ELEMS * 2 + sOff0, Bhi + gB0 + (K0)); \
    CP16(sb + 2 * MAT_ELEMS * 2 + sOff1, Bhi + gB1 + (K0)); \
    asm volatile("cp.async.commit_group;"); \
} while (0)

    LOAD_STAGE(0, 0);

    const int NSTAGE = D_MODEL / BK;
    for (int s = 0; s < NSTAGE; ++s) {
        asm volatile("cp.async.wait_group 0;" ::: "memory");
        __syncthreads();
        if (s + 1 < NSTAGE) LOAD_STAGE(s + 1, (uint32_t)(s + 1) * BK);

        const uint32_t sb = s_base[s & 1];
        const uint32_t aBaseH = sb + (aRow * SK + aCol) * 2;
        const uint32_t aBaseL = aBaseH + MAT_ELEMS * 2;
        const uint32_t bBaseH = sb + 2 * MAT_ELEMS * 2 + (bRow * SK + bCol) * 2;

#pragma unroll
        for (int ks = 0; ks < 2; ++ks) {
            uint32_t ah[4][4], al[4][4], bh[4][2];
#pragma unroll
            for (int mf = 0; mf < 4; ++mf) {
                uint32_t off = (uint32_t)(mf * 16 * SK + ks * 16) * 2;
                LDSM4(ah[mf][0], ah[mf][1], ah[mf][2], ah[mf][3], aBaseH + off);
                LDSM4(al[mf][0], al[mf][1], al[mf][2], al[mf][3], aBaseL + off);
            }
#pragma unroll
            for (int p = 0; p < 2; ++p) {
                uint32_t off = (uint32_t)(p * 16 * SK + ks * 16) * 2;
                LDSM4(bh[2 * p][0], bh[2 * p][1], bh[2 * p + 1][0], bh[2 * p + 1][1], bBaseH + off);
            }
#pragma unroll
            for (int mf = 0; mf < 4; ++mf)
#pragma unroll
                for (int nf = 0; nf < 4; ++nf)
                    MMA_F16(acc[mf][nf], ah[mf], bh[nf]);
#pragma unroll
            for (int mf = 0; mf < 4; ++mf)
#pragma unroll
                for (int nf = 0; nf < 4; ++nf)
                    MMA_F16(acc[mf][nf], al[mf], bh[nf]);
        }
    }

    const int l4 = lane >> 2, l2 = (lane & 3) * 2;
#pragma unroll
    for (int mf = 0; mf < 4; ++mf) {
#pragma unroll
        for (int nf = 0; nf < 4; ++nf) {
            const int r = m0 + wm * 64 + mf * 16 + l4;
            const int c = n0 + wn * 32 + nf * 8 + l2;
            const float bx = bias[c], by = bias[c + 1];
            float v00 = acc[mf][nf][0] + bx, v01 = acc[mf][nf][1] + by;
            float v10 = acc[mf][nf][2] + bx, v11 = acc[mf][nf][3] + by;
            if (jb.mode == 0) {
                *(float2*)&jb.Cf[(size_t)r * D_MODEL + c] = make_float2(v00, v01);
                *(float2*)&jb.Cf[(size_t)(r + 8) * D_MODEL + c] = make_float2(v10, v11);
            } else {
                v00 *= jb.oscale; v01 *= jb.oscale; v10 *= jb.oscale; v11 *= jb.oscale;
                const int b = r >> 11, sx = r & (SEQ - 1);
                const int h = c >> 6, d = c & (DK - 1);
                const int bhh = b * HEADS + h;
                if (jb.mode == 1) {
                    __half2 h0 = __floats2half2_rn(v00, v01);
                    __half2 h1 = __floats2half2_rn(v10, v11);
                    size_t o0 = ((size_t)bhh * SEQ + sx) * DK + d;
                    size_t o1 = ((size_t)bhh * SEQ + sx + 8) * DK + d;
                    *(__half2*)&jb.Chi[o0] = h0;
                    *(__half2*)&jb.Chi[o1] = h1;
                    if (jb.Clo) {
                        __half2 L0 = __floats2half2_rn(v00 - __low2float(h0), v01 - __high2float(h0));
                        __half2 L1 = __floats2half2_rn(v10 - __low2float(h1), v11 - __high2float(h1));
                        *(__half2*)&jb.Clo[o0] = L0;
                        *(__half2*)&jb.Clo[o1] = L1;
                    }
                } else {  // mode 2: transposed [bh][d][s], hi only
                    size_t base = (size_t)bhh * DK * SEQ;
                    float vv[4] = {v00, v01, v10, v11};
                    int dd[4] = {d, d + 1, d, d + 1};
                    int ss[4] = {sx, sx, sx + 8, sx + 8};
#pragma unroll
                    for (int e = 0; e < 4; e++)
                        jb.Chi[base + (size_t)dd[e] * SEQ + ss[e]] = __float2half_rn(vv[e]);
                }
            }
        }
    }
}

// ---------------------------------------------------------------------------
// base-2 fast exp: e^x where y = x*log2e already formed; 2^j * e^t
// exp2_fast(0) == 1.0f exactly (t=0 -> p=1, e=2^0).
// ---------------------------------------------------------------------------
__device__ __forceinline__ float exp2_fast(float y)
{
    float jf = y + 12582912.f;
    float t = (y - (jf - 12582912.f)) * 0.6931471805599453f;
    float p = fmaf(t, 0.041666668f, 0.16666667f);
    p = fmaf(t, p, 0.5f);
    p = fmaf(t, p, 1.0f);
    p = fmaf(t, p, 1.0f);
    int e = (__float_as_int(jf) - 0x4B400000 + 127) << 23;
    return p * __int_as_float(e);
}

// ---------------------------------------------------------------------------
// Flash attention (causal), fp16. QK: Qh+Ql 2-term. PV: Ph single-term.
// Conditional rescale (bit-identical when no new max). fp16 hi/lo output.
// ---------------------------------------------------------------------------
#define FSK 72
#define FTILE (64 * FSK)
#define FSTAGE (2 * FTILE)

__global__ void __launch_bounds__(128, 4) flash_mma_kernel(
    const fp16* __restrict__ Qh, const fp16* __restrict__ Ql,
    const fp16* __restrict__ Kh, const fp16* __restrict__ Vh,
    fp16* __restrict__ Ohi, fp16* __restrict__ Olo)
{
    extern __shared__ __align__(16) fp16 fsm[];
    const int tid = threadIdx.x, lane = tid & 31, w = tid >> 5;
    const int qt = gridDim.x - 1 - blockIdx.x, bh = blockIdx.y;

    const uint32_t sb = (uint32_t)__cvta_generic_to_shared(fsm);
    const uint32_t sQh = sb + FSTAGE * 2;               // Q staged in buffer 1
    const uint32_t sQl = sQh + FTILE * 2;

    const size_t gQ = ((size_t)bh * SEQ + (size_t)qt * 64) * DK;
    const size_t gK = (size_t)bh * SEQ * DK;
    const size_t gV = (size_t)bh * DK * SEQ;

#define FLOADQ() do { \
    _Pragma("unroll") \
    for (int i = 0; i < 4; i++) { \
        int idx = tid + i * 128; int rr = idx >> 3; int cc = (idx & 7) * 8; \
        uint32_t so = (uint32_t)(rr * FSK + cc) * 2; \
        CP16(sQh + so, Qh + gQ + rr * DK + cc); \
        CP16(sQl + so, Ql + gQ + rr * DK + cc); \
    } \
} while (0)

#define FLOADKV(S, KT) do { \
    uint32_t st = sb + (uint32_t)(S) * FSTAGE * 2; \
    _Pragma("unroll") \
    for (int i = 0; i < 4; i++) { \
        int idx = tid + i * 128; int rr = idx >> 3; int cc = (idx & 7) * 8; \
        uint32_t so = (uint32_t)(rr * FSK + cc) * 2; \
        CP16(st + so,             Kh + gK + (size_t)((KT) * 64 + rr) * DK + cc); \
        CP16(st + FTILE * 2 + so, Vh + gV + (size_t)rr * SEQ + (KT) * 64 + cc); \
    } \
    asm volatile("cp.async.commit_group;"); \
} while (0)

    FLOADQ();
    FLOADKV(0, 0);

    const uint32_t aOff = (uint32_t)((w * 16 + (lane & 15)) * FSK + (lane >> 4) * 8) * 2;
    const uint32_t bRowOff = (lane & 7) + ((lane >> 4) & 1) * 8;
    const uint32_t bColOff = ((lane >> 3) & 1) * 8;

    const int l4 = lane >> 2, l2 = (lane & 3) * 2;
    const int rowBaseA = w * 16 + l4;
    float m0 = -3.0e38f, m1 = -3.0e38f, l0 = 0.f, l1 = 0.f;
    float o[8][4];
#pragma unroll
    for (int n = 0; n < 8; n++)
#pragma unroll
        for (int c = 0; c < 4; c++) o[n][c] = 0.f;

    uint32_t qhf[4][4], qlf[4][4];

    for (int kt = 0; kt <= qt; ++kt) {
        asm volatile("cp.async.wait_group 0;" ::: "memory");
        __syncthreads();

        if (kt == 0) {
#pragma unroll
            for (int kk = 0; kk < 4; ++kk) {
                uint32_t off = aOff + (uint32_t)(kk * 16) * 2;
                LDSM4(qhf[kk][0], qhf[kk][1], qhf[kk][2], qhf[kk][3], sQh + off);
                LDSM4(qlf[kk][0], qlf[kk][1], qlf[kk][2], qlf[kk][3], sQl + off);
            }
            __syncthreads();
            if (kt < qt) FLOADKV(1, 1);
        } else {
            if (kt < qt) FLOADKV((kt + 1) & 1, kt + 1);
        }

        const uint32_t stg = sb + (uint32_t)(kt & 1) * FSTAGE * 2;

        float s[8][4];
#pragma unroll
        for (int n = 0; n < 8; n++)
#pragma unroll
            for (int c = 0; c < 4; c++) s[n][c] = 0.f;

#pragma unroll
        for (int kk = 0; kk < 4; ++kk) {
            uint32_t khf[8][2];
#pragma unroll
            for (int p = 0; p < 4; ++p) {
                uint32_t off = (uint32_t)((p * 16 + bRowOff) * FSK + bColOff + kk * 16) * 2;
                LDSM4(khf[2 * p][0], khf[2 * p][1], khf[2 * p + 1][0], khf[2 * p + 1][1], stg + off);
            }
#pragma unroll
            for (int n = 0; n < 8; n++)
                MMA_F16(s[n], qhf[kk], khf[n]);
#pragma unroll
            for (int n = 0; n < 8; n++)
                MMA_F16(s[n], qlf[kk], khf[n]);
        }

        float r0 = -3.0e38f, r1 = -3.0e38f;
#pragma unroll
        for (int n = 0; n < 8; n++) {
            r0 = fmaxf(r0, fmaxf(s[n][0], s[n][1]));
            r1 = fmaxf(r1, fmaxf(s[n][2], s[n][3]));
        }
        r0 = fmaxf(r0, __shfl_xor_sync(0xffffffffu, r0, 1));
        r0 = fmaxf(r0, __shfl_xor_sync(0xffffffffu, r0, 2));
        r1 = fmaxf(r1, __shfl_xor_sync(0xffffffffu, r1, 1));
        r1 = fmaxf(r1, __shfl_xor_sync(0xffffffffu, r1, 2));

        float mn0 = fmaxf(m0, r0), mn1 = fmaxf(m1, r1);
        if ((mn0 > m0) | (mn1 > m1)) {
            // exp2_fast(0)==1.0 exactly, so skipping when no new max is bit-identical
            float c0 = exp2_fast(fmaxf((m0 - mn0) * LOG2E, -126.f));
            float c1 = exp2_fast(fmaxf((m1 - mn1) * LOG2E, -126.f));
            l0 *= c0; l1 *= c1;
#pragma unroll
            for (int n = 0; n < 8; n++) {
                o[n][0] *= c0; o[n][1] *= c0;
                o[n][2] *= c1; o[n][3] *= c1;
            }
            m0 = mn0; m1 = mn1;
        }
        const float ym0 = m0 * LOG2E, ym1 = m1 * LOG2E;

        const bool diag = (kt == qt);
        float ls0 = 0.f, ls1 = 0.f;
#pragma unroll
        for (int n = 0; n < 8; n++) {
            float p0 = exp2_fast(fmaf(s[n][0], LOG2E, -ym0));
            float p1 = exp2_fast(fmaf(s[n][1], LOG2E, -ym0));
            float p2 = exp2_fast(fmaf(s[n][2], LOG2E, -ym1));
            float p3 = exp2_fast(fmaf(s[n][3], LOG2E, -ym1));
            if (diag) {
                int cb = n * 8 + l2;
                if (cb > rowBaseA) p0 = 0.f;
                if (cb + 1 > rowBaseA) p1 = 0.f;
                if (cb > rowBaseA + 8) p2 = 0.f;
                if (cb + 1 > rowBaseA + 8) p3 = 0.f;
            }
            s[n][0] = p0; s[n][1] = p1; s[n][2] = p2; s[n][3] = p3;
            ls0 += p0 + p1; ls1 += p2 + p3;
        }
        l0 += ls0;
        l1 += ls1;

        // pack P (hi only) into A-fragments
        uint32_t aPh[4][4];
#pragma unroll
        for (int kk = 0; kk < 4; ++kk) {
            const int n0i = 2 * kk, n1i = 2 * kk + 1;
            __half2 h;
            h = __floats2half2_rn(s[n0i][0], s[n0i][1]); aPh[kk][0] = *(uint32_t*)&h;
            h = __floats2half2_rn(s[n0i][2], s[n0i][3]); aPh[kk][1] = *(uint32_t*)&h;
            h = __floats2half2_rn(s[n1i][0], s[n1i][1]); aPh[kk][2] = *(uint32_t*)&h;
            h = __floats2half2_rn(s[n1i][2], s[n1i][3]); aPh[kk][3] = *(uint32_t*)&h;
        }

#pragma unroll
        for (int kk = 0; kk < 4; ++kk) {
            uint32_t vhf[8][2];
#pragma unroll
            for (int p = 0; p < 4; ++p) {
                uint32_t off = (uint32_t)((p * 16 + bRowOff) * FSK + bColOff + kk * 16) * 2;
                LDSM4(vhf[2 * p][0], vhf[2 * p][1], vhf[2 * p + 1][0], vhf[2 * p + 1][1],
                      stg + FTILE * 2 + off);
            }
#pragma unroll
            for (int n = 0; n < 8; n++)
                MMA_F16(o[n], aPh[kk], vhf[n]);
        }
    }

    l0 += __shfl_xor_sync(0xffffffffu, l0, 1);
    l0 += __shfl_xor_sync(0xffffffffu, l0, 2);
    l1 += __shfl_xor_sync(0xffffffffu, l1, 1);
    l1 += __shfl_xor_sync(0xffffffffu, l1, 2);
    const float inv0 = 1.f / l0, inv1 = 1.f / l1;

    const int b = bh >> 4, hh = bh & 15;
    const int grow = qt * 64 + rowBaseA;
    const size_t rbase0 = ((size_t)b * SEQ + grow) * D_MODEL + hh * DK;
    const size_t rbase1 = rbase0 + (size_t)8 * D_MODEL;
#pragma unroll
    for (int n = 0; n < 8; n++) {
        const int d = n * 8 + l2;
        float v0 = o[n][0] * inv0, v1 = o[n][1] * inv0;
        float v2 = o[n][2] * inv1, v3 = o[n][3] * inv1;
        __half2 h0 = __floats2half2_rn(v0, v1);
        __half2 h1 = __floats2half2_rn(v2, v3);
        __half2 L0 = __floats2half2_rn(v0 - __low2float(h0), v1 - __high2float(h0));
        __half2 L1 = __floats2half2_rn(v2 - __low2float(h1), v3 - __high2float(h1));
        *(__half2*)&Ohi[rbase0 + d] = h0;
        *(__half2*)&Olo[rbase0 + d] = L0;
        *(__half2*)&Ohi[rbase1 + d] = h1;
        *(__half2*)&Olo[rbase1 + d] = L1;
    }
}

// ---------------------------------------------------------------------------
extern "C" void kernel_launch(void* const* d_in, const int* in_sizes, int n_in,
                              void* d_out, int out_size)
{
    const float* query = (const float*)d_in[0];
    const float* key   = (const float*)d_in[1];
    const float* value = (const float*)d_in[2];
    // d_in[3] = mask (causal handled analytically)
    const float* Wq = (const float*)d_in[4];
    const float* bq = (const float*)d_in[5];
    const float* Wk = (const float*)d_in[6];
    const float* bk = (const float*)d_in[7];
    const float* Wv = (const float*)d_in[8];
    const float* bv = (const float*)d_in[9];
    const float* Wo = (const float*)d_in[10];
    const float* bo = (const float*)d_in[11];
    float* out = (float*)d_out;

    fp16 *ahi, *alo, *whi, *qhi, *qlo, *khi, *vhi;
    cudaGetSymbolAddress((void**)&ahi, g_ahi);
    cudaGetSymbolAddress((void**)&alo, g_alo);
    cudaGetSymbolAddress((void**)&whi, g_whi);
    cudaGetSymbolAddress((void**)&qhi, g_qhi);
    cudaGetSymbolAddress((void**)&qlo, g_qlo);
    cudaGetSymbolAddress((void**)&khi, g_khi);
    cudaGetSymbolAddress((void**)&vhi, g_vhi);

    const size_t ASTRIDE = (size_t)M_ROWS * D_MODEL;
    const size_t WSTRIDE = (size_t)D_MODEL * D_MODEL;

    const int gemm_smem = STAGE_ELEMS * 2 * 2;     // 61440 B
    cudaFuncSetAttribute(gemm_mma_kernel,
                         cudaFuncAttributeMaxDynamicSharedMemorySize, gemm_smem);
    const int flash_smem = 2 * FSTAGE * 2;         // 36864 B
    cudaFuncSetAttribute(flash_mma_kernel,
                         cudaFuncAttributeMaxDynamicSharedMemorySize, flash_smem);

    // 1. convert activations
    ConvA ca;
    ca.in[0] = query; ca.in[1] = key; ca.in[2] = value;
    for (int i = 0; i < 3; i++) { ca.hi[i] = ahi + i * ASTRIDE; ca.lo[i] = alo + i * ASTRIDE; }
    convert_act_kernel<<<dim3(M_ROWS * D_MODEL / 4096, 1, 3), 256>>>(ca);

    // 2. convert + transpose weights (hi only)
    ConvW cw;
    cw.W[0] = Wq; cw.W[1] = Wk; cw.W[2] = Wv; cw.W[3] = Wo;
    for (int i = 0; i < 4; i++) cw.hi[i] = whi + i * WSTRIDE;
    convert_wT_kernel<<<dim3(32, 32, 4), dim3(32, 8)>>>(cw);

    // 3-5. QKV projections
    dim3 gg(D_MODEL / BN, M_ROWS / BM);
    GemmJob jq = { ahi + 0 * ASTRIDE, alo + 0 * ASTRIDE, whi + 0 * WSTRIDE,
                   bq, nullptr, qhi, qlo, 1, 0.125f };
    gemm_mma_kernel<<<gg, 256, gemm_smem>>>(jq);
    GemmJob jk = { ahi + 1 * ASTRIDE, alo + 1 * ASTRIDE, whi + 1 * WSTRIDE,
                   bk, nullptr, khi, nullptr, 1, 1.0f };
    gemm_mma_kernel<<<gg, 256, gemm_smem>>>(jk);
    GemmJob jv = { ahi + 2 * ASTRIDE, alo + 2 * ASTRIDE, whi + 2 * WSTRIDE,
                   bv, nullptr, vhi, nullptr, 2, 1.0f };
    gemm_mma_kernel<<<gg, 256, gemm_smem>>>(jv);

    // 6. flash attention — writes O as fp16 hi/lo into activation set 0
    flash_mma_kernel<<<dim3(SEQ / 64, BH), 128, flash_smem>>>(
        qhi, qlo, khi, vhi, ahi, alo);

    // 7. output projection — fp32 out
    GemmJob jo = { ahi, alo, whi + 3 * WSTRIDE,
                   bo, out, nullptr, nullptr, 0, 1.0f };
    gemm_mma_kernel<<<gg, 256, gemm_smem>>>(jo);
}

// round 13
// speedup vs baseline: 1.1801x; 1.0843x over previous
#include <cuda_runtime.h>
#include <cuda_fp16.h>
#include <stdint.h>
#include <math.h>

#define D_MODEL 1024
#define HEADS 16
#define DK 64
#define BATCH 2
#define SEQ 2048
#define M_ROWS (BATCH * SEQ)   // 4096
#define BH (BATCH * HEADS)     // 32
#define LOG2E 1.4426950408889634f

typedef __half fp16;

// ---------------- scratch (static device globals; no allocation) -------------
__device__ fp16 g_ahi[(size_t)3 * M_ROWS * D_MODEL];   // activation sets (hi)
__device__ fp16 g_alo[(size_t)3 * M_ROWS * D_MODEL];   // activation sets (lo)
__device__ fp16 g_whi[(size_t)4 * D_MODEL * D_MODEL];  // W^T hi only [N][K]
__device__ fp16 g_qhi[(size_t)BH * SEQ * DK];          // [bh][s][d], pre-scaled 0.125
__device__ fp16 g_khi[(size_t)BH * SEQ * DK];          // hi only
__device__ fp16 g_vhi[(size_t)BH * DK * SEQ];          // transposed [bh][d][s], hi only

// ---------------------------------------------------------------------------
// MMA building blocks (mma.sync path — tcgen05 unavailable: harness PTX
// targets sm_103 without the 'a' feature suffix). fp16 inputs, fp32 accum.
// ---------------------------------------------------------------------------
#define LDSM4(R0, R1, R2, R3, ADDR) \
    asm volatile("ldmatrix.sync.aligned.m8n8.x4.shared.b16 {%0,%1,%2,%3}, [%4];" \
        : "=r"(R0), "=r"(R1), "=r"(R2), "=r"(R3) : "r"(ADDR))

#define MMA_F16(D, A, B) \
    asm volatile("mma.sync.aligned.m16n8k16.row.col.f32.f16.f16.f32 " \
        "{%0,%1,%2,%3}, {%4,%5,%6,%7}, {%8,%9}, {%0,%1,%2,%3};" \
        : "+f"(D[0]), "+f"(D[1]), "+f"(D[2]), "+f"(D[3]) \
        : "r"(A[0]), "r"(A[1]), "r"(A[2]), "r"(A[3]), "r"(B[0]), "r"(B[1]))

#define CP16(DST, SRC) \
    asm volatile("cp.async.cg.shared.global [%0], [%1], 16;" :: "r"(DST), "l"(SRC))

// ---------------------------------------------------------------------------
// merged converts (grid.z selects tensor)
// ---------------------------------------------------------------------------
struct ConvA { const float* in[3]; fp16* hi[3]; fp16* lo[3]; };

__global__ void __launch_bounds__(256) convert_act_kernel(ConvA a)
{
    const int z = blockIdx.z;
    const float* in = a.in[z];
    fp16* hi = a.hi[z];
    fp16* lo = a.lo[z];
    const int base = blockIdx.x * 1024 + threadIdx.x;
#pragma unroll
    for (int jj = 0; jj < 4; jj++) {
        int i = base + jj * 256;
        float4 v = ((const float4*)in)[i];
        float f[4] = {v.x, v.y, v.z, v.w};
        union { fp16 h[4]; uint2 u; } uh, ul;
#pragma unroll
        for (int j = 0; j < 4; j++) {
            uh.h[j] = __float2half_rn(f[j]);
            ul.h[j] = __float2half_rn(f[j] - __half2float(uh.h[j]));
        }
        ((uint2*)hi)[i] = uh.u;
        ((uint2*)lo)[i] = ul.u;
    }
}

struct ConvW { const float* W[4]; fp16* hi[4]; };

__global__ void convert_wT_kernel(ConvW a)
{
    __shared__ float t[32][33];
    const int z = blockIdx.z;
    const float* W = a.W[z];
    fp16* hiT = a.hi[z];
    const int k0 = blockIdx.x * 32, n0 = blockIdx.y * 32;
    const int tx = threadIdx.x, ty = threadIdx.y;
#pragma unroll
    for (int j = 0; j < 4; j++)
        t[ty + j * 8][tx] = W[(size_t)(k0 + ty + j * 8) * D_MODEL + n0 + tx];
    __syncthreads();
#pragma unroll
    for (int j = 0; j < 4; j++) {
        float v = t[tx][ty + j * 8];
        hiT[(size_t)(n0 + ty + j * 8) * D_MODEL + k0 + tx] = __float2half_rn(v);
    }
}

// ---------------------------------------------------------------------------
// GEMM via mma.sync fp16 (2-term split): C = A*W^T + bias — unchanged.
// ---------------------------------------------------------------------------
#define BM 128
#define BN 128
#define BK 32
#define SK 40
#define MAT_ELEMS (128 * SK)
#define STAGE_ELEMS (3 * MAT_ELEMS)

struct GemmJob {
    const fp16 *Ah, *Al, *Bh;
    const float* bias;
    float* Cf;
    fp16 *Chi, *Clo;
    int mode;
    float oscale;
};

__global__ void __launch_bounds__(256, 2) gemm_mma_kernel(GemmJob jb)
{
    extern __shared__ __align__(16) fp16 sm[];
    const fp16* __restrict__ Ahi = jb.Ah;
    const fp16* __restrict__ Alo = jb.Al;
    const fp16* __restrict__ Bhi = jb.Bh;
    const float* __restrict__ bias = jb.bias;

    const int tid = threadIdx.x;
    const int lane = tid & 31, warp = tid >> 5;
    const int wm = warp >> 2, wn = warp & 3;
    const int m0 = blockIdx.y * BM, n0 = blockIdx.x * BN;

    const int r0 = tid >> 2;
    const int cc0 = (tid & 3) * 8;

    uint32_t s_base[2];
    s_base[0] = (uint32_t)__cvta_generic_to_shared(sm);
    s_base[1] = s_base[0] + STAGE_ELEMS * 2;

    const uint32_t gA0 = (uint32_t)(m0 + r0) * D_MODEL + cc0;
    const uint32_t gA1 = (uint32_t)(m0 + r0 + 64) * D_MODEL + cc0;
    const uint32_t gB0 = (uint32_t)(n0 + r0) * D_MODEL + cc0;
    const uint32_t gB1 = (uint32_t)(n0 + r0 + 64) * D_MODEL + cc0;
    const uint32_t sOff0 = (uint32_t)(r0 * SK + cc0) * 2;
    const uint32_t sOff1 = (uint32_t)((r0 + 64) * SK + cc0) * 2;

    float acc[4][4][4];
#pragma unroll
    for (int a = 0; a < 4; a++)
#pragma unroll
        for (int b = 0; b < 4; b++)
#pragma unroll
            for (int c = 0; c < 4; c++) acc[a][b][c] = 0.f;

    const uint32_t aRow = wm * 64 + (lane & 15);
    const uint32_t aCol = (lane >> 4) * 8;
    const uint32_t bRow = wn * 32 + (lane & 7) + ((lane >> 4) & 1) * 8;
    const uint32_t bCol = ((lane >> 3) & 1) * 8;

#define LOAD_STAGE(S, K0) do { \
    uint32_t sb = s_base[(S) & 1]; \
    CP16(sb + sOff0,                     Ahi + gA0 + (K0)); \
    CP16(sb + sOff1,                     Ahi + gA1 + (K0)); \
    CP16(sb + MAT_ELEMS * 2 + sOff0,     Alo + gA0 + (K0)); \
    CP16(sb + MAT_ELEMS * 2 + sOff1,     Alo + gA1 + (K0)); \
    CP16(sb + 2 * MAT_ELEMS * 2 + sOff0, Bhi + gB0 + (K0)); \
    CP16(sb + 2 * MAT_ELEMS * 2 + sOff1, Bhi + gB1 + (K0)); \
    asm volatile("cp.async.commit_group;"); \
} while (0)

    LOAD_STAGE(0, 0);

    const int NSTAGE = D_MODEL / BK;
    for (int s = 0; s < NSTAGE; ++s) {
        asm volatile("cp.async.wait_group 0;" ::: "memory");
        __syncthreads();
        if (s + 1 < NSTAGE) LOAD_STAGE(s + 1, (uint32_t)(s + 1) * BK);

        const uint32_t sb = s_base[s & 1];
        const uint32_t aBaseH = sb + (aRow * SK + aCol) * 2;
        const uint32_t aBaseL = aBaseH + MAT_ELEMS * 2;
        const uint32_t bBaseH = sb + 2 * MAT_ELEMS * 2 + (bRow * SK + bCol) * 2;

#pragma unroll
        for (int ks = 0; ks < 2; ++ks) {
            uint32_t ah[4][4], al[4][4], bh[4][2];
#pragma unroll
            for (int mf = 0; mf < 4; ++mf) {
                uint32_t off = (uint32_t)(mf * 16 * SK + ks * 16) * 2;
                LDSM4(ah[mf][0], ah[mf][1], ah[mf][2], ah[mf][3], aBaseH + off);
                LDSM4(al[mf][0], al[mf][1], al[mf][2], al[mf][3], aBaseL + off);
            }
#pragma unroll
            for (int p = 0; p < 2; ++p) {
                uint32_t off = (uint32_t)(p * 16 * SK + ks * 16) * 2;
                LDSM4(bh[2 * p][0], bh[2 * p][1], bh[2 * p + 1][0], bh[2 * p + 1][1], bBaseH + off);
            }
#pragma unroll
            for (int mf = 0; mf < 4; ++mf)
#pragma unroll
                for (int nf = 0; nf < 4; ++nf)
                    MMA_F16(acc[mf][nf], ah[mf], bh[nf]);
#pragma unroll
            for (int mf = 0; mf < 4; ++mf)
#pragma unroll
                for (int nf = 0; nf < 4; ++nf)
                    MMA_F16(acc[mf][nf], al[mf], bh[nf]);
        }
    }

    const int l4 = lane >> 2, l2 = (lane & 3) * 2;
#pragma unroll
    for (int mf = 0; mf < 4; ++mf) {
#pragma unroll
        for (int nf = 0; nf < 4; ++nf) {
            const int r = m0 + wm * 64 + mf * 16 + l4;
            const int c = n0 + wn * 32 + nf * 8 + l2;
            const float bx = bias[c], by = bias[c + 1];
            float v00 = acc[mf][nf][0] + bx, v01 = acc[mf][nf][1] + by;
            float v10 = acc[mf][nf][2] + bx, v11 = acc[mf][nf][3] + by;
            if (jb.mode == 0) {
                *(float2*)&jb.Cf[(size_t)r * D_MODEL + c] = make_float2(v00, v01);
                *(float2*)&jb.Cf[(size_t)(r + 8) * D_MODEL + c] = make_float2(v10, v11);
            } else {
                v00 *= jb.oscale; v01 *= jb.oscale; v10 *= jb.oscale; v11 *= jb.oscale;
                const int b = r >> 11, sx = r & (SEQ - 1);
                const int h = c >> 6, d = c & (DK - 1);
                const int bhh = b * HEADS + h;
                if (jb.mode == 1) {
                    __half2 h0 = __floats2half2_rn(v00, v01);
                    __half2 h1 = __floats2half2_rn(v10, v11);
                    size_t o0 = ((size_t)bhh * SEQ + sx) * DK + d;
                    size_t o1 = ((size_t)bhh * SEQ + sx + 8) * DK + d;
                    *(__half2*)&jb.Chi[o0] = h0;
                    *(__half2*)&jb.Chi[o1] = h1;
                    if (jb.Clo) {
                        __half2 L0 = __floats2half2_rn(v00 - __low2float(h0), v01 - __high2float(h0));
                        __half2 L1 = __floats2half2_rn(v10 - __low2float(h1), v11 - __high2float(h1));
                        *(__half2*)&jb.Clo[o0] = L0;
                        *(__half2*)&jb.Clo[o1] = L1;
                    }
                } else {  // mode 2: transposed [bh][d][s], hi only
                    size_t base = (size_t)bhh * DK * SEQ;
                    float vv[4] = {v00, v01, v10, v11};
                    int dd[4] = {d, d + 1, d, d + 1};
                    int ss[4] = {sx, sx, sx + 8, sx + 8};
#pragma unroll
                    for (int e = 0; e < 4; e++)
                        jb.Chi[base + (size_t)dd[e] * SEQ + ss[e]] = __float2half_rn(vv[e]);
                }
            }
        }
    }
}

// ---------------------------------------------------------------------------
// base-2 fast exp: e^x with y = x*log2e preformed; exp2_fast(0)==1.0 exactly.
// ---------------------------------------------------------------------------
__device__ __forceinline__ float exp2_fast(float y)
{
    float jf = y + 12582912.f;
    float t = (y - (jf - 12582912.f)) * 0.6931471805599453f;
    float p = fmaf(t, 0.041666668f, 0.16666667f);
    p = fmaf(t, p, 0.5f);
    p = fmaf(t, p, 1.0f);
    p = fmaf(t, p, 1.0f);
    int e = (__float_as_int(jf) - 0x4B400000 + 127) << 23;
    return p * __int_as_float(e);
}

// ---------------------------------------------------------------------------
// Flash attention (causal), fp16. QK: Qh single-term. PV: Ph single-term.
// Conditional rescale. fp16 hi/lo output for the O-projection.
// ---------------------------------------------------------------------------
#define FSK 72
#define FTILE (64 * FSK)
#define FSTAGE (2 * FTILE)

__global__ void __launch_bounds__(128, 4) flash_mma_kernel(
    const fp16* __restrict__ Qh,
    const fp16* __restrict__ Kh, const fp16* __restrict__ Vh,
    fp16* __restrict__ Ohi, fp16* __restrict__ Olo)
{
    extern __shared__ __align__(16) fp16 fsm[];
    const int tid = threadIdx.x, lane = tid & 31, w = tid >> 5;
    const int qt = gridDim.x - 1 - blockIdx.x, bh = blockIdx.y;

    const uint32_t sb = (uint32_t)__cvta_generic_to_shared(fsm);
    const uint32_t sQh = sb + FSTAGE * 2;               // Q staged in buffer 1

    const size_t gQ = ((size_t)bh * SEQ + (size_t)qt * 64) * DK;
    const size_t gK = (size_t)bh * SEQ * DK;
    const size_t gV = (size_t)bh * DK * SEQ;

#define FLOADQ() do { \
    _Pragma("unroll") \
    for (int i = 0; i < 4; i++) { \
        int idx = tid + i * 128; int rr = idx >> 3; int cc = (idx & 7) * 8; \
        uint32_t so = (uint32_t)(rr * FSK + cc) * 2; \
        CP16(sQh + so, Qh + gQ + rr * DK + cc); \
    } \
} while (0)

#define FLOADKV(S, KT) do { \
    uint32_t st = sb + (uint32_t)(S) * FSTAGE * 2; \
    _Pragma("unroll") \
    for (int i = 0; i < 4; i++) { \
        int idx = tid + i * 128; int rr = idx >> 3; int cc = (idx & 7) * 8; \
        uint32_t so = (uint32_t)(rr * FSK + cc) * 2; \
        CP16(st + so,             Kh + gK + (size_t)((KT) * 64 + rr) * DK + cc); \
        CP16(st + FTILE * 2 + so, Vh + gV + (size_t)rr * SEQ + (KT) * 64 + cc); \
    } \
    asm volatile("cp.async.commit_group;"); \
} while (0)

    FLOADQ();
    FLOADKV(0, 0);

    const uint32_t aOff = (uint32_t)((w * 16 + (lane & 15)) * FSK + (lane >> 4) * 8) * 2;
    const uint32_t bRowOff = (lane & 7) + ((lane >> 4) & 1) * 8;
    const uint32_t bColOff = ((lane >> 3) & 1) * 8;

    const int l4 = lane >> 2, l2 = (lane & 3) * 2;
    const int rowBaseA = w * 16 + l4;
    float m0 = -3.0e38f, m1 = -3.0e38f, l0 = 0.f, l1 = 0.f;
    float o[8][4];
#pragma unroll
    for (int n = 0; n < 8; n++)
#pragma unroll
        for (int c = 0; c < 4; c++) o[n][c] = 0.f;

    uint32_t qhf[4][4];

    for (int kt = 0; kt <= qt; ++kt) {
        asm volatile("cp.async.wait_group 0;" ::: "memory");
        __syncthreads();

        if (kt == 0) {
#pragma unroll
            for (int kk = 0; kk < 4; ++kk) {
                uint32_t off = aOff + (uint32_t)(kk * 16) * 2;
                LDSM4(qhf[kk][0], qhf[kk][1], qhf[kk][2], qhf[kk][3], sQh + off);
            }
            __syncthreads();
            if (kt < qt) FLOADKV(1, 1);
        } else {
            if (kt < qt) FLOADKV((kt + 1) & 1, kt + 1);
        }

        const uint32_t stg = sb + (uint32_t)(kt & 1) * FSTAGE * 2;

        float s[8][4];
#pragma unroll
        for (int n = 0; n < 8; n++)
#pragma unroll
            for (int c = 0; c < 4; c++) s[n][c] = 0.f;

#pragma unroll
        for (int kk = 0; kk < 4; ++kk) {
            uint32_t khf[8][2];
#pragma unroll
            for (int p = 0; p < 4; ++p) {
                uint32_t off = (uint32_t)((p * 16 + bRowOff) * FSK + bColOff + kk * 16) * 2;
                LDSM4(khf[2 * p][0], khf[2 * p][1], khf[2 * p + 1][0], khf[2 * p + 1][1], stg + off);
            }
#pragma unroll
            for (int n = 0; n < 8; n++)
                MMA_F16(s[n], qhf[kk], khf[n]);
        }

        float r0 = -3.0e38f, r1 = -3.0e38f;
#pragma unroll
        for (int n = 0; n < 8; n++) {
            r0 = fmaxf(r0, fmaxf(s[n][0], s[n][1]));
            r1 = fmaxf(r1, fmaxf(s[n][2], s[n][3]));
        }
        r0 = fmaxf(r0, __shfl_xor_sync(0xffffffffu, r0, 1));
        r0 = fmaxf(r0, __shfl_xor_sync(0xffffffffu, r0, 2));
        r1 = fmaxf(r1, __shfl_xor_sync(0xffffffffu, r1, 1));
        r1 = fmaxf(r1, __shfl_xor_sync(0xffffffffu, r1, 2));

        float mn0 = fmaxf(m0, r0), mn1 = fmaxf(m1, r1);
        if ((mn0 > m0) | (mn1 > m1)) {
            float c0 = exp2_fast(fmaxf((m0 - mn0) * LOG2E, -126.f));
            float c1 = exp2_fast(fmaxf((m1 - mn1) * LOG2E, -126.f));
            l0 *= c0; l1 *= c1;
#pragma unroll
            for (int n = 0; n < 8; n++) {
                o[n][0] *= c0; o[n][1] *= c0;
                o[n][2] *= c1; o[n][3] *= c1;
            }
            m0 = mn0; m1 = mn1;
        }
        const float ym0 = m0 * LOG2E, ym1 = m1 * LOG2E;

        const bool diag = (kt == qt);
        float ls0 = 0.f, ls1 = 0.f;
#pragma unroll
        for (int n = 0; n < 8; n++) {
            float p0 = exp2_fast(fmaf(s[n][0], LOG2E, -ym0));
            float p1 = exp2_fast(fmaf(s[n][1], LOG2E, -ym0));
            float p2 = exp2_fast(fmaf(s[n][2], LOG2E, -ym1));
            float p3 = exp2_fast(fmaf(s[n][3], LOG2E, -ym1));
            if (diag) {
                int cb = n * 8 + l2;
                if (cb > rowBaseA) p0 = 0.f;
                if (cb + 1 > rowBaseA) p1 = 0.f;
                if (cb > rowBaseA + 8) p2 = 0.f;
                if (cb + 1 > rowBaseA + 8) p3 = 0.f;
            }
            s[n][0] = p0; s[n][1] = p1; s[n][2] = p2; s[n][3] = p3;
            ls0 += p0 + p1; ls1 += p2 + p3;
        }
        l0 += ls0;
        l1 += ls1;

        // pack P (hi only) into A-fragments
        uint32_t aPh[4][4];
#pragma unroll
        for (int kk = 0; kk < 4; ++kk) {
            const int n0i = 2 * kk, n1i = 2 * kk + 1;
            __half2 h;
            h = __floats2half2_rn(s[n0i][0], s[n0i][1]); aPh[kk][0] = *(uint32_t*)&h;
            h = __floats2half2_rn(s[n0i][2], s[n0i][3]); aPh[kk][1] = *(uint32_t*)&h;
            h = __floats2half2_rn(s[n1i][0], s[n1i][1]); aPh[kk][2] = *(uint32_t*)&h;
            h = __floats2half2_rn(s[n1i][2], s[n1i][3]); aPh[kk][3] = *(uint32_t*)&h;
        }

#pragma unroll
        for (int kk = 0; kk < 4; ++kk) {
            uint32_t vhf[8][2];
#pragma unroll
            for (int p = 0; p < 4; ++p) {
                uint32_t off = (uint32_t)((p * 16 + bRowOff) * FSK + bColOff + kk * 16) * 2;
                LDSM4(vhf[2 * p][0], vhf[2 * p][1], vhf[2 * p + 1][0], vhf[2 * p + 1][1],
                      stg + FTILE * 2 + off);
            }
#pragma unroll
            for (int n = 0; n < 8; n++)
                MMA_F16(o[n], aPh[kk], vhf[n]);
        }
    }

    l0 += __shfl_xor_sync(0xffffffffu, l0, 1);
    l0 += __shfl_xor_sync(0xffffffffu, l0, 2);
    l1 += __shfl_xor_sync(0xffffffffu, l1, 1);
    l1 += __shfl_xor_sync(0xffffffffu, l1, 2);
    const float inv0 = 1.f / l0, inv1 = 1.f / l1;

    const int b = bh >> 4, hh = bh & 15;
    const int grow = qt * 64 + rowBaseA;
    const size_t rbase0 = ((size_t)b * SEQ + grow) * D_MODEL + hh * DK;
    const size_t rbase1 = rbase0 + (size_t)8 * D_MODEL;
#pragma unroll
    for (int n = 0; n < 8; n++) {
        const int d = n * 8 + l2;
        float v0 = o[n][0] * inv0, v1 = o[n][1] * inv0;
        float v2 = o[n][2] * inv1, v3 = o[n][3] * inv1;
        __half2 h0 = __floats2half2_rn(v0, v1);
        __half2 h1 = __floats2half2_rn(v2, v3);
        __half2 L0 = __floats2half2_rn(v0 - __low2float(h0), v1 - __high2float(h0));
        __half2 L1 = __floats2half2_rn(v2 - __low2float(h1), v3 - __high2float(h1));
        *(__half2*)&Ohi[rbase0 + d] = h0;
        *(__half2*)&Olo[rbase0 + d] = L0;
        *(__half2*)&Ohi[rbase1 + d] = h1;
        *(__half2*)&Olo[rbase1 + d] = L1;
    }
}

// ---------------------------------------------------------------------------
extern "C" void kernel_launch(void* const* d_in, const int* in_sizes, int n_in,
                              void* d_out, int out_size)
{
    const float* query = (const float*)d_in[0];
    const float* key   = (const float*)d_in[1];
    const float* value = (const float*)d_in[2];
    // d_in[3] = mask (causal handled analytically)
    const float* Wq = (const float*)d_in[4];
    const float* bq = (const float*)d_in[5];
    const float* Wk = (const float*)d_in[6];
    const float* bk = (const float*)d_in[7];
    const float* Wv = (const float*)d_in[8];
    const float* bv = (const float*)d_in[9];
    const float* Wo = (const float*)d_in[10];
    const float* bo = (const float*)d_in[11];
    float* out = (float*)d_out;

    fp16 *ahi, *alo, *whi, *qhi, *khi, *vhi;
    cudaGetSymbolAddress((void**)&ahi, g_ahi);
    cudaGetSymbolAddress((void**)&alo, g_alo);
    cudaGetSymbolAddress((void**)&whi, g_whi);
    cudaGetSymbolAddress((void**)&qhi, g_qhi);
    cudaGetSymbolAddress((void**)&khi, g_khi);
    cudaGetSymbolAddress((void**)&vhi, g_vhi);

    const size_t ASTRIDE = (size_t)M_ROWS * D_MODEL;
    const size_t WSTRIDE = (size_t)D_MODEL * D_MODEL;

    const int gemm_smem = STAGE_ELEMS * 2 * 2;     // 61440 B
    cudaFuncSetAttribute(gemm_mma_kernel,
                         cudaFuncAttributeMaxDynamicSharedMemorySize, gemm_smem);
    const int flash_smem = 2 * FSTAGE * 2;         // 36864 B
    cudaFuncSetAttribute(flash_mma_kernel,
                         cudaFuncAttributeMaxDynamicSharedMemorySize, flash_smem);

    // 1. convert activations
    ConvA ca;
    ca.in[0] = query; ca.in[1] = key; ca.in[2] = value;
    for (int i = 0; i < 3; i++) { ca.hi[i] = ahi + i * ASTRIDE; ca.lo[i] = alo + i * ASTRIDE; }
    convert_act_kernel<<<dim3(M_ROWS * D_MODEL / 4096, 1, 3), 256>>>(ca);

    // 2. convert + transpose weights (hi only)
    ConvW cw;
    cw.W[0] = Wq; cw.W[1] = Wk; cw.W[2] = Wv; cw.W[3] = Wo;
    for (int i = 0; i < 4; i++) cw.hi[i] = whi + i * WSTRIDE;
    convert_wT_kernel<<<dim3(32, 32, 4), dim3(32, 8)>>>(cw);

    // 3-5. QKV projections (Q hi only — flash QK is single-term now)
    dim3 gg(D_MODEL / BN, M_ROWS / BM);
    GemmJob jq = { ahi + 0 * ASTRIDE, alo + 0 * ASTRIDE, whi + 0 * WSTRIDE,
                   bq, nullptr, qhi, nullptr, 1, 0.125f };
    gemm_mma_kernel<<<gg, 256, gemm_smem>>>(jq);
    GemmJob jk = { ahi + 1 * ASTRIDE, alo + 1 * ASTRIDE, whi + 1 * WSTRIDE,
                   bk, nullptr, khi, nullptr, 1, 1.0f };
    gemm_mma_kernel<<<gg, 256, gemm_smem>>>(jk);
    GemmJob jv = { ahi + 2 * ASTRIDE, alo + 2 * ASTRIDE, whi + 2 * WSTRIDE,
                   bv, nullptr, vhi, nullptr, 2, 1.0f };
    gemm_mma_kernel<<<gg, 256, gemm_smem>>>(jv);

    // 6. flash attention — writes O as fp16 hi/lo into activation set 0
    flash_mma_kernel<<<dim3(SEQ / 64, BH), 128, flash_smem>>>(
        qhi, khi, vhi, ahi, alo);

    // 7. output projection — fp32 out
    GemmJob jo = { ahi, alo, whi + 3 * WSTRIDE,
                   bo, out, nullptr, nullptr, 0, 1.0f };
    gemm_mma_kernel<<<gg, 256, gemm_smem>>>(jo);
}

// round 14
// speedup vs baseline: 1.5504x; 1.3138x over previous
#include <cuda_runtime.h>
#include <cuda_fp16.h>
#include <stdint.h>
#include <math.h>

#define D_MODEL 1024
#define HEADS 16
#define DK 64
#define BATCH 2
#define SEQ 2048
#define M_ROWS (BATCH * SEQ)   // 4096
#define BH (BATCH * HEADS)     // 32
#define LOG2E 1.4426950408889634f

typedef __half fp16;

// ---------------- scratch (static device globals; no allocation) -------------
__device__ fp16 g_ahi[(size_t)3 * M_ROWS * D_MODEL];   // activation sets (hi only)
__device__ fp16 g_whi[(size_t)4 * D_MODEL * D_MODEL];  // W^T hi only [N][K]
__device__ fp16 g_qhi[(size_t)BH * SEQ * DK];          // [bh][s][d], pre-scaled 0.125
__device__ fp16 g_khi[(size_t)BH * SEQ * DK];
__device__ fp16 g_vhi[(size_t)BH * DK * SEQ];          // transposed [bh][d][s]

// ---------------------------------------------------------------------------
// MMA building blocks (mma.sync path — tcgen05 unavailable: harness PTX
// targets sm_103 without the 'a' feature suffix). fp16 inputs, fp32 accum.
// ---------------------------------------------------------------------------
#define LDSM4(R0, R1, R2, R3, ADDR) \
    asm volatile("ldmatrix.sync.aligned.m8n8.x4.shared.b16 {%0,%1,%2,%3}, [%4];" \
        : "=r"(R0), "=r"(R1), "=r"(R2), "=r"(R3) : "r"(ADDR))

#define MMA_F16(D, A, B) \
    asm volatile("mma.sync.aligned.m16n8k16.row.col.f32.f16.f16.f32 " \
        "{%0,%1,%2,%3}, {%4,%5,%6,%7}, {%8,%9}, {%0,%1,%2,%3};" \
        : "+f"(D[0]), "+f"(D[1]), "+f"(D[2]), "+f"(D[3]) \
        : "r"(A[0]), "r"(A[1]), "r"(A[2]), "r"(A[3]), "r"(B[0]), "r"(B[1]))

#define CP16(DST, SRC) \
    asm volatile("cp.async.cg.shared.global [%0], [%1], 16;" :: "r"(DST), "l"(SRC))

// ---------------------------------------------------------------------------
// merged converts (grid.z selects tensor) — hi plane only
// ---------------------------------------------------------------------------
struct ConvA { const float* in[3]; fp16* hi[3]; };

__global__ void __launch_bounds__(256) convert_act_kernel(ConvA a)
{
    const int z = blockIdx.z;
    const float* in = a.in[z];
    fp16* hi = a.hi[z];
    const int base = blockIdx.x * 1024 + threadIdx.x;
#pragma unroll
    for (int jj = 0; jj < 4; jj++) {
        int i = base + jj * 256;
        float4 v = ((const float4*)in)[i];
        float f[4] = {v.x, v.y, v.z, v.w};
        union { fp16 h[4]; uint2 u; } uh;
#pragma unroll
        for (int j = 0; j < 4; j++)
            uh.h[j] = __float2half_rn(f[j]);
        ((uint2*)hi)[i] = uh.u;
    }
}

struct ConvW { const float* W[4]; fp16* hi[4]; };

__global__ void convert_wT_kernel(ConvW a)
{
    __shared__ float t[32][33];
    const int z = blockIdx.z;
    const float* W = a.W[z];
    fp16* hiT = a.hi[z];
    const int k0 = blockIdx.x * 32, n0 = blockIdx.y * 32;
    const int tx = threadIdx.x, ty = threadIdx.y;
#pragma unroll
    for (int j = 0; j < 4; j++)
        t[ty + j * 8][tx] = W[(size_t)(k0 + ty + j * 8) * D_MODEL + n0 + tx];
    __syncthreads();
#pragma unroll
    for (int j = 0; j < 4; j++) {
        float v = t[tx][ty + j * 8];
        hiT[(size_t)(n0 + ty + j * 8) * D_MODEL + k0 + tx] = __float2half_rn(v);
    }
}

// ---------------------------------------------------------------------------
// GEMM via mma.sync fp16, single-term: C = Ah*Wh^T + bias
// mode 0: fp32 C row-major. 1: fp16 head-split hi. 2: transposed V hi.
// ---------------------------------------------------------------------------
#define BM 128
#define BN 128
#define BK 32
#define SK 40
#define MAT_ELEMS (128 * SK)
#define STAGE_ELEMS (2 * MAT_ELEMS)

struct GemmJob {
    const fp16 *Ah, *Bh;
    const float* bias;
    float* Cf;
    fp16 *Chi;
    int mode;
    float oscale;
};

__global__ void __launch_bounds__(256, 2) gemm_mma_kernel(GemmJob jb)
{
    extern __shared__ __align__(16) fp16 sm[];
    const fp16* __restrict__ Ahi = jb.Ah;
    const fp16* __restrict__ Bhi = jb.Bh;
    const float* __restrict__ bias = jb.bias;

    const int tid = threadIdx.x;
    const int lane = tid & 31, warp = tid >> 5;
    const int wm = warp >> 2, wn = warp & 3;
    const int m0 = blockIdx.y * BM, n0 = blockIdx.x * BN;

    const int r0 = tid >> 2;
    const int cc0 = (tid & 3) * 8;

    uint32_t s_base[2];
    s_base[0] = (uint32_t)__cvta_generic_to_shared(sm);
    s_base[1] = s_base[0] + STAGE_ELEMS * 2;

    const uint32_t gA0 = (uint32_t)(m0 + r0) * D_MODEL + cc0;
    const uint32_t gA1 = (uint32_t)(m0 + r0 + 64) * D_MODEL + cc0;
    const uint32_t gB0 = (uint32_t)(n0 + r0) * D_MODEL + cc0;
    const uint32_t gB1 = (uint32_t)(n0 + r0 + 64) * D_MODEL + cc0;
    const uint32_t sOff0 = (uint32_t)(r0 * SK + cc0) * 2;
    const uint32_t sOff1 = (uint32_t)((r0 + 64) * SK + cc0) * 2;

    float acc[4][4][4];
#pragma unroll
    for (int a = 0; a < 4; a++)
#pragma unroll
        for (int b = 0; b < 4; b++)
#pragma unroll
            for (int c = 0; c < 4; c++) acc[a][b][c] = 0.f;

    const uint32_t aRow = wm * 64 + (lane & 15);
    const uint32_t aCol = (lane >> 4) * 8;
    const uint32_t bRow = wn * 32 + (lane & 7) + ((lane >> 4) & 1) * 8;
    const uint32_t bCol = ((lane >> 3) & 1) * 8;

#define LOAD_STAGE(S, K0) do { \
    uint32_t sb = s_base[(S) & 1]; \
    CP16(sb + sOff0,                 Ahi + gA0 + (K0)); \
    CP16(sb + sOff1,                 Ahi + gA1 + (K0)); \
    CP16(sb + MAT_ELEMS * 2 + sOff0, Bhi + gB0 + (K0)); \
    CP16(sb + MAT_ELEMS * 2 + sOff1, Bhi + gB1 + (K0)); \
    asm volatile("cp.async.commit_group;"); \
} while (0)

    LOAD_STAGE(0, 0);

    const int NSTAGE = D_MODEL / BK;
    for (int s = 0; s < NSTAGE; ++s) {
        asm volatile("cp.async.wait_group 0;" ::: "memory");
        __syncthreads();
        if (s + 1 < NSTAGE) LOAD_STAGE(s + 1, (uint32_t)(s + 1) * BK);

        const uint32_t sb = s_base[s & 1];
        const uint32_t aBaseH = sb + (aRow * SK + aCol) * 2;
        const uint32_t bBaseH = sb + MAT_ELEMS * 2 + (bRow * SK + bCol) * 2;

#pragma unroll
        for (int ks = 0; ks < 2; ++ks) {
            uint32_t ah[4][4], bh[4][2];
#pragma unroll
            for (int mf = 0; mf < 4; ++mf) {
                uint32_t off = (uint32_t)(mf * 16 * SK + ks * 16) * 2;
                LDSM4(ah[mf][0], ah[mf][1], ah[mf][2], ah[mf][3], aBaseH + off);
            }
#pragma unroll
            for (int p = 0; p < 2; ++p) {
                uint32_t off = (uint32_t)(p * 16 * SK + ks * 16) * 2;
                LDSM4(bh[2 * p][0], bh[2 * p][1], bh[2 * p + 1][0], bh[2 * p + 1][1], bBaseH + off);
            }
#pragma unroll
            for (int mf = 0; mf < 4; ++mf)
#pragma unroll
                for (int nf = 0; nf < 4; ++nf)
                    MMA_F16(acc[mf][nf], ah[mf], bh[nf]);
        }
    }

    const int l4 = lane >> 2, l2 = (lane & 3) * 2;
#pragma unroll
    for (int mf = 0; mf < 4; ++mf) {
#pragma unroll
        for (int nf = 0; nf < 4; ++nf) {
            const int r = m0 + wm * 64 + mf * 16 + l4;
            const int c = n0 + wn * 32 + nf * 8 + l2;
            const float bx = bias[c], by = bias[c + 1];
            float v00 = acc[mf][nf][0] + bx, v01 = acc[mf][nf][1] + by;
            float v10 = acc[mf][nf][2] + bx, v11 = acc[mf][nf][3] + by;
            if (jb.mode == 0) {
                *(float2*)&jb.Cf[(size_t)r * D_MODEL + c] = make_float2(v00, v01);
                *(float2*)&jb.Cf[(size_t)(r + 8) * D_MODEL + c] = make_float2(v10, v11);
            } else {
                v00 *= jb.oscale; v01 *= jb.oscale; v10 *= jb.oscale; v11 *= jb.oscale;
                const int b = r >> 11, sx = r & (SEQ - 1);
                const int h = c >> 6, d = c & (DK - 1);
                const int bhh = b * HEADS + h;
                if (jb.mode == 1) {
                    __half2 h0 = __floats2half2_rn(v00, v01);
                    __half2 h1 = __floats2half2_rn(v10, v11);
                    size_t o0 = ((size_t)bhh * SEQ + sx) * DK + d;
                    size_t o1 = ((size_t)bhh * SEQ + sx + 8) * DK + d;
                    *(__half2*)&jb.Chi[o0] = h0;
                    *(__half2*)&jb.Chi[o1] = h1;
                } else {  // mode 2: transposed [bh][d][s]
                    size_t base = (size_t)bhh * DK * SEQ;
                    float vv[4] = {v00, v01, v10, v11};
                    int dd[4] = {d, d + 1, d, d + 1};
                    int ss[4] = {sx, sx, sx + 8, sx + 8};
#pragma unroll
                    for (int e = 0; e < 4; e++)
                        jb.Chi[base + (size_t)dd[e] * SEQ + ss[e]] = __float2half_rn(vv[e]);
                }
            }
        }
    }
}

// ---------------------------------------------------------------------------
// base-2 fast exp: e^x with y = x*log2e preformed; exp2_fast(0)==1.0 exactly.
// ---------------------------------------------------------------------------
__device__ __forceinline__ float exp2_fast(float y)
{
    float jf = y + 12582912.f;
    float t = (y - (jf - 12582912.f)) * 0.6931471805599453f;
    float p = fmaf(t, 0.041666668f, 0.16666667f);
    p = fmaf(t, p, 0.5f);
    p = fmaf(t, p, 1.0f);
    p = fmaf(t, p, 1.0f);
    int e = (__float_as_int(jf) - 0x4B400000 + 127) << 23;
    return p * __int_as_float(e);
}

// ---------------------------------------------------------------------------
// Flash attention (causal), fp16 single-term QK and PV. fp16 hi output only.
// ---------------------------------------------------------------------------
#define FSK 72
#define FTILE (64 * FSK)
#define FSTAGE (2 * FTILE)

__global__ void __launch_bounds__(128, 4) flash_mma_kernel(
    const fp16* __restrict__ Qh,
    const fp16* __restrict__ Kh, const fp16* __restrict__ Vh,
    fp16* __restrict__ Ohi)
{
    extern __shared__ __align__(16) fp16 fsm[];
    const int tid = threadIdx.x, lane = tid & 31, w = tid >> 5;
    const int qt = gridDim.x - 1 - blockIdx.x, bh = blockIdx.y;

    const uint32_t sb = (uint32_t)__cvta_generic_to_shared(fsm);
    const uint32_t sQh = sb + FSTAGE * 2;               // Q staged in buffer 1

    const size_t gQ = ((size_t)bh * SEQ + (size_t)qt * 64) * DK;
    const size_t gK = (size_t)bh * SEQ * DK;
    const size_t gV = (size_t)bh * DK * SEQ;

#define FLOADQ() do { \
    _Pragma("unroll") \
    for (int i = 0; i < 4; i++) { \
        int idx = tid + i * 128; int rr = idx >> 3; int cc = (idx & 7) * 8; \
        uint32_t so = (uint32_t)(rr * FSK + cc) * 2; \
        CP16(sQh + so, Qh + gQ + rr * DK + cc); \
    } \
} while (0)

#define FLOADKV(S, KT) do { \
    uint32_t st = sb + (uint32_t)(S) * FSTAGE * 2; \
    _Pragma("unroll") \
    for (int i = 0; i < 4; i++) { \
        int idx = tid + i * 128; int rr = idx >> 3; int cc = (idx & 7) * 8; \
        uint32_t so = (uint32_t)(rr * FSK + cc) * 2; \
        CP16(st + so,             Kh + gK + (size_t)((KT) * 64 + rr) * DK + cc); \
        CP16(st + FTILE * 2 + so, Vh + gV + (size_t)rr * SEQ + (KT) * 64 + cc); \
    } \
    asm volatile("cp.async.commit_group;"); \
} while (0)

    FLOADQ();
    FLOADKV(0, 0);

    const uint32_t aOff = (uint32_t)((w * 16 + (lane & 15)) * FSK + (lane >> 4) * 8) * 2;
    const uint32_t bRowOff = (lane & 7) + ((lane >> 4) & 1) * 8;
    const uint32_t bColOff = ((lane >> 3) & 1) * 8;

    const int l4 = lane >> 2, l2 = (lane & 3) * 2;
    const int rowBaseA = w * 16 + l4;
    float m0 = -3.0e38f, m1 = -3.0e38f, l0 = 0.f, l1 = 0.f;
    float o[8][4];
#pragma unroll
    for (int n = 0; n < 8; n++)
#pragma unroll
        for (int c = 0; c < 4; c++) o[n][c] = 0.f;

    uint32_t qhf[4][4];

    for (int kt = 0; kt <= qt; ++kt) {
        asm volatile("cp.async.wait_group 0;" ::: "memory");
        __syncthreads();

        if (kt == 0) {
#pragma unroll
            for (int kk = 0; kk < 4; ++kk) {
                uint32_t off = aOff + (uint32_t)(kk * 16) * 2;
                LDSM4(qhf[kk][0], qhf[kk][1], qhf[kk][2], qhf[kk][3], sQh + off);
            }
            __syncthreads();
            if (kt < qt) FLOADKV(1, 1);
        } else {
            if (kt < qt) FLOADKV((kt + 1) & 1, kt + 1);
        }

        const uint32_t stg = sb + (uint32_t)(kt & 1) * FSTAGE * 2;

        float s[8][4];
#pragma unroll
        for (int n = 0; n < 8; n++)
#pragma unroll
            for (int c = 0; c < 4; c++) s[n][c] = 0.f;

#pragma unroll
        for (int kk = 0; kk < 4; ++kk) {
            uint32_t khf[8][2];
#pragma unroll
            for (int p = 0; p < 4; ++p) {
                uint32_t off = (uint32_t)((p * 16 + bRowOff) * FSK + bColOff + kk * 16) * 2;
                LDSM4(khf[2 * p][0], khf[2 * p][1], khf[2 * p + 1][0], khf[2 * p + 1][1], stg + off);
            }
#pragma unroll
            for (int n = 0; n < 8; n++)
                MMA_F16(s[n], qhf[kk], khf[n]);
        }

        float r0 = -3.0e38f, r1 = -3.0e38f;
#pragma unroll
        for (int n = 0; n < 8; n++) {
            r0 = fmaxf(r0, fmaxf(s[n][0], s[n][1]));
            r1 = fmaxf(r1, fmaxf(s[n][2], s[n][3]));
        }
        r0 = fmaxf(r0, __shfl_xor_sync(0xffffffffu, r0, 1));
        r0 = fmaxf(r0, __shfl_xor_sync(0xffffffffu, r0, 2));
        r1 = fmaxf(r1, __shfl_xor_sync(0xffffffffu, r1, 1));
        r1 = fmaxf(r1, __shfl_xor_sync(0xffffffffu, r1, 2));

        float mn0 = fmaxf(m0, r0), mn1 = fmaxf(m1, r1);
        if ((mn0 > m0) | (mn1 > m1)) {
            float c0 = exp2_fast(fmaxf((m0 - mn0) * LOG2E, -126.f));
            float c1 = exp2_fast(fmaxf((m1 - mn1) * LOG2E, -126.f));
            l0 *= c0; l1 *= c1;
#pragma unroll
            for (int n = 0; n < 8; n++) {
                o[n][0] *= c0; o[n][1] *= c0;
                o[n][2] *= c1; o[n][3] *= c1;
            }
            m0 = mn0; m1 = mn1;
        }
        const float ym0 = m0 * LOG2E, ym1 = m1 * LOG2E;

        const bool diag = (kt == qt);
        float ls0 = 0.f, ls1 = 0.f;
#pragma unroll
        for (int n = 0; n < 8; n++) {
            float p0 = exp2_fast(fmaf(s[n][0], LOG2E, -ym0));
            float p1 = exp2_fast(fmaf(s[n][1], LOG2E, -ym0));
            float p2 = exp2_fast(fmaf(s[n][2], LOG2E, -ym1));
            float p3 = exp2_fast(fmaf(s[n][3], LOG2E, -ym1));
            if (diag) {
                int cb = n * 8 + l2;
                if (cb > rowBaseA) p0 = 0.f;
                if (cb + 1 > rowBaseA) p1 = 0.f;
                if (cb > rowBaseA + 8) p2 = 0.f;
                if (cb + 1 > rowBaseA + 8) p3 = 0.f;
            }
            s[n][0] = p0; s[n][1] = p1; s[n][2] = p2; s[n][3] = p3;
            ls0 += p0 + p1; ls1 += p2 + p3;
        }
        l0 += ls0;
        l1 += ls1;

        // pack P (hi only) into A-fragments
        uint32_t aPh[4][4];
#pragma unroll
        for (int kk = 0; kk < 4; ++kk) {
            const int n0i = 2 * kk, n1i = 2 * kk + 1;
            __half2 h;
            h = __floats2half2_rn(s[n0i][0], s[n0i][1]); aPh[kk][0] = *(uint32_t*)&h;
            h = __floats2half2_rn(s[n0i][2], s[n0i][3]); aPh[kk][1] = *(uint32_t*)&h;
            h = __floats2half2_rn(s[n1i][0], s[n1i][1]); aPh[kk][2] = *(uint32_t*)&h;
            h = __floats2half2_rn(s[n1i][2], s[n1i][3]); aPh[kk][3] = *(uint32_t*)&h;
        }

#pragma unroll
        for (int kk = 0; kk < 4; ++kk) {
            uint32_t vhf[8][2];
#pragma unroll
            for (int p = 0; p < 4; ++p) {
                uint32_t off = (uint32_t)((p * 16 + bRowOff) * FSK + bColOff + kk * 16) * 2;
                LDSM4(vhf[2 * p][0], vhf[2 * p][1], vhf[2 * p + 1][0], vhf[2 * p + 1][1],
                      stg + FTILE * 2 + off);
            }
#pragma unroll
            for (int n = 0; n < 8; n++)
                MMA_F16(o[n], aPh[kk], vhf[n]);
        }
    }

    l0 += __shfl_xor_sync(0xffffffffu, l0, 1);
    l0 += __shfl_xor_sync(0xffffffffu, l0, 2);
    l1 += __shfl_xor_sync(0xffffffffu, l1, 1);
    l1 += __shfl_xor_sync(0xffffffffu, l1, 2);
    const float inv0 = 1.f / l0, inv1 = 1.f / l1;

    const int b = bh >> 4, hh = bh & 15;
    const int grow = qt * 64 + rowBaseA;
    const size_t rbase0 = ((size_t)b * SEQ + grow) * D_MODEL + hh * DK;
    const size_t rbase1 = rbase0 + (size_t)8 * D_MODEL;
#pragma unroll
    for (int n = 0; n < 8; n++) {
        const int d = n * 8 + l2;
        __half2 h0 = __floats2half2_rn(o[n][0] * inv0, o[n][1] * inv0);
        __half2 h1 = __floats2half2_rn(o[n][2] * inv1, o[n][3] * inv1);
        *(__half2*)&Ohi[rbase0 + d] = h0;
        *(__half2*)&Ohi[rbase1 + d] = h1;
    }
}

// ---------------------------------------------------------------------------
extern "C" void kernel_launch(void* const* d_in, const int* in_sizes, int n_in,
                              void* d_out, int out_size)
{
    const float* query = (const float*)d_in[0];
    const float* key   = (const float*)d_in[1];
    const float* value = (const float*)d_in[2];
    // d_in[3] = mask (causal handled analytically)
    const float* Wq = (const float*)d_in[4];
    const float* bq = (const float*)d_in[5];
    const float* Wk = (const float*)d_in[6];
    const float* bk = (const float*)d_in[7];
    const float* Wv = (const float*)d_in[8];
    const float* bv = (const float*)d_in[9];
    const float* Wo = (const float*)d_in[10];
    const float* bo = (const float*)d_in[11];
    float* out = (float*)d_out;

    fp16 *ahi, *whi, *qhi, *khi, *vhi;
    cudaGetSymbolAddress((void**)&ahi, g_ahi);
    cudaGetSymbolAddress((void**)&whi, g_whi);
    cudaGetSymbolAddress((void**)&qhi, g_qhi);
    cudaGetSymbolAddress((void**)&khi, g_khi);
    cudaGetSymbolAddress((void**)&vhi, g_vhi);

    const size_t ASTRIDE = (size_t)M_ROWS * D_MODEL;
    const size_t WSTRIDE = (size_t)D_MODEL * D_MODEL;

    const int gemm_smem = STAGE_ELEMS * 2 * 2;     // 40960 B
    cudaFuncSetAttribute(gemm_mma_kernel,
                         cudaFuncAttributeMaxDynamicSharedMemorySize, gemm_smem);
    const int flash_smem = 2 * FSTAGE * 2;         // 36864 B
    cudaFuncSetAttribute(flash_mma_kernel,
                         cudaFuncAttributeMaxDynamicSharedMemorySize, flash_smem);

    // 1. convert activations (hi only)
    ConvA ca;
    ca.in[0] = query; ca.in[1] = key; ca.in[2] = value;
    for (int i = 0; i < 3; i++) ca.hi[i] = ahi + i * ASTRIDE;
    convert_act_kernel<<<dim3(M_ROWS * D_MODEL / 4096, 1, 3), 256>>>(ca);

    // 2. convert + transpose weights (hi only)
    ConvW cw;
    cw.W[0] = Wq; cw.W[1] = Wk; cw.W[2] = Wv; cw.W[3] = Wo;
    for (int i = 0; i < 4; i++) cw.hi[i] = whi + i * WSTRIDE;
    convert_wT_kernel<<<dim3(32, 32, 4), dim3(32, 8)>>>(cw);

    // 3-5. QKV projections (single-term)
    dim3 gg(D_MODEL / BN, M_ROWS / BM);
    GemmJob jq = { ahi + 0 * ASTRIDE, whi + 0 * WSTRIDE, bq, nullptr, qhi, 1, 0.125f };
    gemm_mma_kernel<<<gg, 256, gemm_smem>>>(jq);
    GemmJob jk = { ahi + 1 * ASTRIDE, whi + 1 * WSTRIDE, bk, nullptr, khi, 1, 1.0f };
    gemm_mma_kernel<<<gg, 256, gemm_smem>>>(jk);
    GemmJob jv = { ahi + 2 * ASTRIDE, whi + 2 * WSTRIDE, bv, nullptr, vhi, 2, 1.0f };
    gemm_mma_kernel<<<gg, 256, gemm_smem>>>(jv);

    // 6. flash attention — writes O (hi) into activation set 0
    flash_mma_kernel<<<dim3(SEQ / 64, BH), 128, flash_smem>>>(
        qhi, khi, vhi, ahi);

    // 7. output projection — fp32 out
    GemmJob jo = { ahi, whi + 3 * WSTRIDE, bo, out, nullptr, 0, 1.0f };
    gemm_mma_kernel<<<gg, 256, gemm_smem>>>(jo);
}

// round 15
// speedup vs baseline: 1.6258x; 1.0486x over previous
#include <cuda_runtime.h>
#include <cuda_fp16.h>
#include <stdint.h>
#include <math.h>

#define D_MODEL 1024
#define HEADS 16
#define DK 64
#define BATCH 2
#define SEQ 2048
#define M_ROWS (BATCH * SEQ)   // 4096
#define BH (BATCH * HEADS)     // 32
#define LOG2E 1.4426950408889634f

typedef __half fp16;

// ---------------- scratch (static device globals; no allocation) -------------
__device__ fp16 g_ahi[(size_t)3 * M_ROWS * D_MODEL];   // activation sets (hi only)
__device__ fp16 g_whi[(size_t)4 * D_MODEL * D_MODEL];  // W^T hi only [N][K]
__device__ fp16 g_qhi[(size_t)BH * SEQ * DK];          // [bh][s][d], pre-scaled 0.125
__device__ fp16 g_khi[(size_t)BH * SEQ * DK];
__device__ fp16 g_vhi[(size_t)BH * DK * SEQ];          // transposed [bh][d][s]

// ---------------------------------------------------------------------------
// MMA building blocks (mma.sync path — tcgen05 unavailable: harness PTX
// targets sm_103 without the 'a' feature suffix). fp16 inputs, fp32 accum.
// ---------------------------------------------------------------------------
#define LDSM4(R0, R1, R2, R3, ADDR) \
    asm volatile("ldmatrix.sync.aligned.m8n8.x4.shared.b16 {%0,%1,%2,%3}, [%4];" \
        : "=r"(R0), "=r"(R1), "=r"(R2), "=r"(R3) : "r"(ADDR))

#define MMA_F16(D, A, B) \
    asm volatile("mma.sync.aligned.m16n8k16.row.col.f32.f16.f16.f32 " \
        "{%0,%1,%2,%3}, {%4,%5,%6,%7}, {%8,%9}, {%0,%1,%2,%3};" \
        : "+f"(D[0]), "+f"(D[1]), "+f"(D[2]), "+f"(D[3]) \
        : "r"(A[0]), "r"(A[1]), "r"(A[2]), "r"(A[3]), "r"(B[0]), "r"(B[1]))

#define CP16(DST, SRC) \
    asm volatile("cp.async.cg.shared.global [%0], [%1], 16;" :: "r"(DST), "l"(SRC))

// ---------------------------------------------------------------------------
// merged converts (grid.z selects tensor) — hi plane only
// ---------------------------------------------------------------------------
struct ConvA { const float* in[3]; fp16* hi[3]; };

__global__ void __launch_bounds__(256) convert_act_kernel(ConvA a)
{
    const int z = blockIdx.z;
    const float* in = a.in[z];
    fp16* hi = a.hi[z];
    const int base = blockIdx.x * 1024 + threadIdx.x;
#pragma unroll
    for (int jj = 0; jj < 4; jj++) {
        int i = base + jj * 256;
        float4 v = ((const float4*)in)[i];
        float f[4] = {v.x, v.y, v.z, v.w};
        union { fp16 h[4]; uint2 u; } uh;
#pragma unroll
        for (int j = 0; j < 4; j++)
            uh.h[j] = __float2half_rn(f[j]);
        ((uint2*)hi)[i] = uh.u;
    }
}

struct ConvW { const float* W[4]; fp16* hi[4]; };

__global__ void convert_wT_kernel(ConvW a)
{
    __shared__ float t[32][33];
    const int z = blockIdx.z;
    const float* W = a.W[z];
    fp16* hiT = a.hi[z];
    const int k0 = blockIdx.x * 32, n0 = blockIdx.y * 32;
    const int tx = threadIdx.x, ty = threadIdx.y;
#pragma unroll
    for (int j = 0; j < 4; j++)
        t[ty + j * 8][tx] = W[(size_t)(k0 + ty + j * 8) * D_MODEL + n0 + tx];
    __syncthreads();
#pragma unroll
    for (int j = 0; j < 4; j++) {
        float v = t[tx][ty + j * 8];
        hiT[(size_t)(n0 + ty + j * 8) * D_MODEL + k0 + tx] = __float2half_rn(v);
    }
}

// ---------------------------------------------------------------------------
// GEMM via mma.sync fp16, single-term: C = Ah*Wh^T + bias
// BK=64 per stage (8 stages) — half the barrier count of BK=32.
// mode 0: fp32 C row-major. 1: fp16 head-split hi. 2: transposed V hi.
// ---------------------------------------------------------------------------
#define BM 128
#define BN 128
#define BK 64
#define GSK 72                          // padded row stride (fp16) for 64-wide rows
#define MAT_ELEMS (128 * GSK)           // 9216 fp16 per matrix tile
#define STAGE_ELEMS (2 * MAT_ELEMS)     // A + B

struct GemmJob {
    const fp16 *Ah, *Bh;
    const float* bias;
    float* Cf;
    fp16 *Chi;
    int mode;
    float oscale;
};

__global__ void __launch_bounds__(256, 2) gemm_mma_kernel(GemmJob jb)
{
    extern __shared__ __align__(16) fp16 sm[];
    const fp16* __restrict__ Ahi = jb.Ah;
    const fp16* __restrict__ Bhi = jb.Bh;
    const float* __restrict__ bias = jb.bias;

    const int tid = threadIdx.x;
    const int lane = tid & 31, warp = tid >> 5;
    const int wm = warp >> 2, wn = warp & 3;
    const int m0 = blockIdx.y * BM, n0 = blockIdx.x * BN;

    uint32_t s_base[2];
    s_base[0] = (uint32_t)__cvta_generic_to_shared(sm);
    s_base[1] = s_base[0] + STAGE_ELEMS * 2;

    // loader: 1024 16B-chunks per matrix tile; 4 per thread per matrix.
    // chunk idx: row = idx>>3 (0..127), col8 = (idx&7)*8 fp16.
    const uint32_t lrow = (uint32_t)(tid >> 3);          // base rows 0..31 (+32*i)
    const uint32_t lcol = (uint32_t)(tid & 7) * 8;
    const uint32_t sOffB = (lrow * GSK + lcol) * 2;
    const uint32_t gOffA = lrow * D_MODEL + lcol;        // + m0*D_MODEL later
    const uint32_t gOffB = lrow * D_MODEL + lcol;

    float acc[4][4][4];
#pragma unroll
    for (int a = 0; a < 4; a++)
#pragma unroll
        for (int b = 0; b < 4; b++)
#pragma unroll
            for (int c = 0; c < 4; c++) acc[a][b][c] = 0.f;

    const uint32_t aRow = wm * 64 + (lane & 15);
    const uint32_t aCol = (lane >> 4) * 8;
    const uint32_t bRow = wn * 32 + (lane & 7) + ((lane >> 4) & 1) * 8;
    const uint32_t bCol = ((lane >> 3) & 1) * 8;

#define LOAD_STAGE(S, K0) do { \
    uint32_t sb = s_base[(S) & 1]; \
    _Pragma("unroll") \
    for (int i = 0; i < 4; i++) { \
        uint32_t so = sOffB + (uint32_t)(i * 32) * GSK * 2; \
        CP16(sb + so, Ahi + (uint32_t)(m0 + i * 32) * D_MODEL + gOffA + (K0)); \
        CP16(sb + MAT_ELEMS * 2 + so, \
             Bhi + (uint32_t)(n0 + i * 32) * D_MODEL + gOffB + (K0)); \
    } \
    asm volatile("cp.async.commit_group;"); \
} while (0)

    LOAD_STAGE(0, 0);

    const int NSTAGE = D_MODEL / BK;   // 8
    for (int s = 0; s < NSTAGE; ++s) {
        asm volatile("cp.async.wait_group 0;" ::: "memory");
        __syncthreads();
        if (s + 1 < NSTAGE) LOAD_STAGE(s + 1, (uint32_t)(s + 1) * BK);

        const uint32_t sb = s_base[s & 1];
        const uint32_t aBaseH = sb + (aRow * GSK + aCol) * 2;
        const uint32_t bBaseH = sb + MAT_ELEMS * 2 + (bRow * GSK + bCol) * 2;

#pragma unroll
        for (int ks = 0; ks < 4; ++ks) {
            uint32_t ah[4][4], bh[4][2];
#pragma unroll
            for (int mf = 0; mf < 4; ++mf) {
                uint32_t off = (uint32_t)(mf * 16 * GSK + ks * 16) * 2;
                LDSM4(ah[mf][0], ah[mf][1], ah[mf][2], ah[mf][3], aBaseH + off);
            }
#pragma unroll
            for (int p = 0; p < 2; ++p) {
                uint32_t off = (uint32_t)(p * 16 * GSK + ks * 16) * 2;
                LDSM4(bh[2 * p][0], bh[2 * p][1], bh[2 * p + 1][0], bh[2 * p + 1][1], bBaseH + off);
            }
#pragma unroll
            for (int mf = 0; mf < 4; ++mf)
#pragma unroll
                for (int nf = 0; nf < 4; ++nf)
                    MMA_F16(acc[mf][nf], ah[mf], bh[nf]);
        }
    }

    const int l4 = lane >> 2, l2 = (lane & 3) * 2;
#pragma unroll
    for (int mf = 0; mf < 4; ++mf) {
#pragma unroll
        for (int nf = 0; nf < 4; ++nf) {
            const int r = m0 + wm * 64 + mf * 16 + l4;
            const int c = n0 + wn * 32 + nf * 8 + l2;
            const float bx = bias[c], by = bias[c + 1];
            float v00 = acc[mf][nf][0] + bx, v01 = acc[mf][nf][1] + by;
            float v10 = acc[mf][nf][2] + bx, v11 = acc[mf][nf][3] + by;
            if (jb.mode == 0) {
                *(float2*)&jb.Cf[(size_t)r * D_MODEL + c] = make_float2(v00, v01);
                *(float2*)&jb.Cf[(size_t)(r + 8) * D_MODEL + c] = make_float2(v10, v11);
            } else {
                v00 *= jb.oscale; v01 *= jb.oscale; v10 *= jb.oscale; v11 *= jb.oscale;
                const int b = r >> 11, sx = r & (SEQ - 1);
                const int h = c >> 6, d = c & (DK - 1);
                const int bhh = b * HEADS + h;
                if (jb.mode == 1) {
                    __half2 h0 = __floats2half2_rn(v00, v01);
                    __half2 h1 = __floats2half2_rn(v10, v11);
                    size_t o0 = ((size_t)bhh * SEQ + sx) * DK + d;
                    size_t o1 = ((size_t)bhh * SEQ + sx + 8) * DK + d;
                    *(__half2*)&jb.Chi[o0] = h0;
                    *(__half2*)&jb.Chi[o1] = h1;
                } else {  // mode 2: transposed [bh][d][s]
                    size_t base = (size_t)bhh * DK * SEQ;
                    float vv[4] = {v00, v01, v10, v11};
                    int dd[4] = {d, d + 1, d, d + 1};
                    int ss[4] = {sx, sx, sx + 8, sx + 8};
#pragma unroll
                    for (int e = 0; e < 4; e++)
                        jb.Chi[base + (size_t)dd[e] * SEQ + ss[e]] = __float2half_rn(vv[e]);
                }
            }
        }
    }
}

// ---------------------------------------------------------------------------
// base-2 fast exp: e^x with y = x*log2e preformed; exp2_fast(0)==1.0 exactly.
// ---------------------------------------------------------------------------
__device__ __forceinline__ float exp2_fast(float y)
{
    float jf = y + 12582912.f;
    float t = (y - (jf - 12582912.f)) * 0.6931471805599453f;
    float p = fmaf(t, 0.041666668f, 0.16666667f);
    p = fmaf(t, p, 0.5f);
    p = fmaf(t, p, 1.0f);
    p = fmaf(t, p, 1.0f);
    int e = (__float_as_int(jf) - 0x4B400000 + 127) << 23;
    return p * __int_as_float(e);
}

// ---------------------------------------------------------------------------
// Flash attention (causal), fp16 single-term QK and PV — unchanged R14.
// ---------------------------------------------------------------------------
#define FSK 72
#define FTILE (64 * FSK)
#define FSTAGE (2 * FTILE)

__global__ void __launch_bounds__(128, 4) flash_mma_kernel(
    const fp16* __restrict__ Qh,
    const fp16* __restrict__ Kh, const fp16* __restrict__ Vh,
    fp16* __restrict__ Ohi)
{
    extern __shared__ __align__(16) fp16 fsm[];
    const int tid = threadIdx.x, lane = tid & 31, w = tid >> 5;
    const int qt = gridDim.x - 1 - blockIdx.x, bh = blockIdx.y;

    const uint32_t sb = (uint32_t)__cvta_generic_to_shared(fsm);
    const uint32_t sQh = sb + FSTAGE * 2;               // Q staged in buffer 1

    const size_t gQ = ((size_t)bh * SEQ + (size_t)qt * 64) * DK;
    const size_t gK = (size_t)bh * SEQ * DK;
    const size_t gV = (size_t)bh * DK * SEQ;

#define FLOADQ() do { \
    _Pragma("unroll") \
    for (int i = 0; i < 4; i++) { \
        int idx = tid + i * 128; int rr = idx >> 3; int cc = (idx & 7) * 8; \
        uint32_t so = (uint32_t)(rr * FSK + cc) * 2; \
        CP16(sQh + so, Qh + gQ + rr * DK + cc); \
    } \
} while (0)

#define FLOADKV(S, KT) do { \
    uint32_t st = sb + (uint32_t)(S) * FSTAGE * 2; \
    _Pragma("unroll") \
    for (int i = 0; i < 4; i++) { \
        int idx = tid + i * 128; int rr = idx >> 3; int cc = (idx & 7) * 8; \
        uint32_t so = (uint32_t)(rr * FSK + cc) * 2; \
        CP16(st + so,             Kh + gK + (size_t)((KT) * 64 + rr) * DK + cc); \
        CP16(st + FTILE * 2 + so, Vh + gV + (size_t)rr * SEQ + (KT) * 64 + cc); \
    } \
    asm volatile("cp.async.commit_group;"); \
} while (0)

    FLOADQ();
    FLOADKV(0, 0);

    const uint32_t aOff = (uint32_t)((w * 16 + (lane & 15)) * FSK + (lane >> 4) * 8) * 2;
    const uint32_t bRowOff = (lane & 7) + ((lane >> 4) & 1) * 8;
    const uint32_t bColOff = ((lane >> 3) & 1) * 8;

    const int l4 = lane >> 2, l2 = (lane & 3) * 2;
    const int rowBaseA = w * 16 + l4;
    float m0 = -3.0e38f, m1 = -3.0e38f, l0 = 0.f, l1 = 0.f;
    float o[8][4];
#pragma unroll
    for (int n = 0; n < 8; n++)
#pragma unroll
        for (int c = 0; c < 4; c++) o[n][c] = 0.f;

    uint32_t qhf[4][4];

    for (int kt = 0; kt <= qt; ++kt) {
        asm volatile("cp.async.wait_group 0;" ::: "memory");
        __syncthreads();

        if (kt == 0) {
#pragma unroll
            for (int kk = 0; kk < 4; ++kk) {
                uint32_t off = aOff + (uint32_t)(kk * 16) * 2;
                LDSM4(qhf[kk][0], qhf[kk][1], qhf[kk][2], qhf[kk][3], sQh + off);
            }
            __syncthreads();
            if (kt < qt) FLOADKV(1, 1);
        } else {
            if (kt < qt) FLOADKV((kt + 1) & 1, kt + 1);
        }

        const uint32_t stg = sb + (uint32_t)(kt & 1) * FSTAGE * 2;

        float s[8][4];
#pragma unroll
        for (int n = 0; n < 8; n++)
#pragma unroll
            for (int c = 0; c < 4; c++) s[n][c] = 0.f;

#pragma unroll
        for (int kk = 0; kk < 4; ++kk) {
            uint32_t khf[8][2];
#pragma unroll
            for (int p = 0; p < 4; ++p) {
                uint32_t off = (uint32_t)((p * 16 + bRowOff) * FSK + bColOff + kk * 16) * 2;
                LDSM4(khf[2 * p][0], khf[2 * p][1], khf[2 * p + 1][0], khf[2 * p + 1][1], stg + off);
            }
#pragma unroll
            for (int n = 0; n < 8; n++)
                MMA_F16(s[n], qhf[kk], khf[n]);
        }

        float r0 = -3.0e38f, r1 = -3.0e38f;
#pragma unroll
        for (int n = 0; n < 8; n++) {
            r0 = fmaxf(r0, fmaxf(s[n][0], s[n][1]));
            r1 = fmaxf(r1, fmaxf(s[n][2], s[n][3]));
        }
        r0 = fmaxf(r0, __shfl_xor_sync(0xffffffffu, r0, 1));
        r0 = fmaxf(r0, __shfl_xor_sync(0xffffffffu, r0, 2));
        r1 = fmaxf(r1, __shfl_xor_sync(0xffffffffu, r1, 1));
        r1 = fmaxf(r1, __shfl_xor_sync(0xffffffffu, r1, 2));

        float mn0 = fmaxf(m0, r0), mn1 = fmaxf(m1, r1);
        if ((mn0 > m0) | (mn1 > m1)) {
            float c0 = exp2_fast(fmaxf((m0 - mn0) * LOG2E, -126.f));
            float c1 = exp2_fast(fmaxf((m1 - mn1) * LOG2E, -126.f));
            l0 *= c0; l1 *= c1;
#pragma unroll
            for (int n = 0; n < 8; n++) {
                o[n][0] *= c0; o[n][1] *= c0;
                o[n][2] *= c1; o[n][3] *= c1;
            }
            m0 = mn0; m1 = mn1;
        }
        const float ym0 = m0 * LOG2E, ym1 = m1 * LOG2E;

        const bool diag = (kt == qt);
        float ls0 = 0.f, ls1 = 0.f;
#pragma unroll
        for (int n = 0; n < 8; n++) {
            float p0 = exp2_fast(fmaf(s[n][0], LOG2E, -ym0));
            float p1 = exp2_fast(fmaf(s[n][1], LOG2E, -ym0));
            float p2 = exp2_fast(fmaf(s[n][2], LOG2E, -ym1));
            float p3 = exp2_fast(fmaf(s[n][3], LOG2E, -ym1));
            if (diag) {
                int cb = n * 8 + l2;
                if (cb > rowBaseA) p0 = 0.f;
                if (cb + 1 > rowBaseA) p1 = 0.f;
                if (cb > rowBaseA + 8) p2 = 0.f;
                if (cb + 1 > rowBaseA + 8) p3 = 0.f;
            }
            s[n][0] = p0; s[n][1] = p1; s[n][2] = p2; s[n][3] = p3;
            ls0 += p0 + p1; ls1 += p2 + p3;
        }
        l0 += ls0;
        l1 += ls1;

        uint32_t aPh[4][4];
#pragma unroll
        for (int kk = 0; kk < 4; ++kk) {
            const int n0i = 2 * kk, n1i = 2 * kk + 1;
            __half2 h;
            h = __floats2half2_rn(s[n0i][0], s[n0i][1]); aPh[kk][0] = *(uint32_t*)&h;
            h = __floats2half2_rn(s[n0i][2], s[n0i][3]); aPh[kk][1] = *(uint32_t*)&h;
            h = __floats2half2_rn(s[n1i][0], s[n1i][1]); aPh[kk][2] = *(uint32_t*)&h;
            h = __floats2half2_rn(s[n1i][2], s[n1i][3]); aPh[kk][3] = *(uint32_t*)&h;
        }

#pragma unroll
        for (int kk = 0; kk < 4; ++kk) {
            uint32_t vhf[8][2];
#pragma unroll
            for (int p = 0; p < 4; ++p) {
                uint32_t off = (uint32_t)((p * 16 + bRowOff) * FSK + bColOff + kk * 16) * 2;
                LDSM4(vhf[2 * p][0], vhf[2 * p][1], vhf[2 * p + 1][0], vhf[2 * p + 1][1],
                      stg + FTILE * 2 + off);
            }
#pragma unroll
            for (int n = 0; n < 8; n++)
                MMA_F16(o[n], aPh[kk], vhf[n]);
        }
    }

    l0 += __shfl_xor_sync(0xffffffffu, l0, 1);
    l0 += __shfl_xor_sync(0xffffffffu, l0, 2);
    l1 += __shfl_xor_sync(0xffffffffu, l1, 1);
    l1 += __shfl_xor_sync(0xffffffffu, l1, 2);
    const float inv0 = 1.f / l0, inv1 = 1.f / l1;

    const int b = bh >> 4, hh = bh & 15;
    const int grow = qt * 64 + rowBaseA;
    const size_t rbase0 = ((size_t)b * SEQ + grow) * D_MODEL + hh * DK;
    const size_t rbase1 = rbase0 + (size_t)8 * D_MODEL;
#pragma unroll
    for (int n = 0; n < 8; n++) {
        const int d = n * 8 + l2;
        __half2 h0 = __floats2half2_rn(o[n][0] * inv0, o[n][1] * inv0);
        __half2 h1 = __floats2half2_rn(o[n][2] * inv1, o[n][3] * inv1);
        *(__half2*)&Ohi[rbase0 + d] = h0;
        *(__half2*)&Ohi[rbase1 + d] = h1;
    }
}

// ---------------------------------------------------------------------------
extern "C" void kernel_launch(void* const* d_in, const int* in_sizes, int n_in,
                              void* d_out, int out_size)
{
    const float* query = (const float*)d_in[0];
    const float* key   = (const float*)d_in[1];
    const float* value = (const float*)d_in[2];
    // d_in[3] = mask (causal handled analytically)
    const float* Wq = (const float*)d_in[4];
    const float* bq = (const float*)d_in[5];
    const float* Wk = (const float*)d_in[6];
    const float* bk = (const float*)d_in[7];
    const float* Wv = (const float*)d_in[8];
    const float* bv = (const float*)d_in[9];
    const float* Wo = (const float*)d_in[10];
    const float* bo = (const float*)d_in[11];
    float* out = (float*)d_out;

    fp16 *ahi, *whi, *qhi, *khi, *vhi;
    cudaGetSymbolAddress((void**)&ahi, g_ahi);
    cudaGetSymbolAddress((void**)&whi, g_whi);
    cudaGetSymbolAddress((void**)&qhi, g_qhi);
    cudaGetSymbolAddress((void**)&khi, g_khi);
    cudaGetSymbolAddress((void**)&vhi, g_vhi);

    const size_t ASTRIDE = (size_t)M_ROWS * D_MODEL;
    const size_t WSTRIDE = (size_t)D_MODEL * D_MODEL;

    const int gemm_smem = STAGE_ELEMS * 2 * 2;     // 73728 B (x2 CTAs = 147KB/SM)
    cudaFuncSetAttribute(gemm_mma_kernel,
                         cudaFuncAttributeMaxDynamicSharedMemorySize, gemm_smem);
    const int flash_smem = 2 * FSTAGE * 2;         // 36864 B
    cudaFuncSetAttribute(flash_mma_kernel,
                         cudaFuncAttributeMaxDynamicSharedMemorySize, flash_smem);

    // 1. convert activations (hi only)
    ConvA ca;
    ca.in[0] = query; ca.in[1] = key; ca.in[2] = value;
    for (int i = 0; i < 3; i++) ca.hi[i] = ahi + i * ASTRIDE;
    convert_act_kernel<<<dim3(M_ROWS * D_MODEL / 4096, 1, 3), 256>>>(ca);

    // 2. convert + transpose weights (hi only)
    ConvW cw;
    cw.W[0] = Wq; cw.W[1] = Wk; cw.W[2] = Wv; cw.W[3] = Wo;
    for (int i = 0; i < 4; i++) cw.hi[i] = whi + i * WSTRIDE;
    convert_wT_kernel<<<dim3(32, 32, 4), dim3(32, 8)>>>(cw);

    // 3-5. QKV projections (single-term, BK=64)
    dim3 gg(D_MODEL / BN, M_ROWS / BM);
    GemmJob jq = { ahi + 0 * ASTRIDE, whi + 0 * WSTRIDE, bq, nullptr, qhi, 1, 0.125f };
    gemm_mma_kernel<<<gg, 256, gemm_smem>>>(jq);
    GemmJob jk = { ahi + 1 * ASTRIDE, whi + 1 * WSTRIDE, bk, nullptr, khi, 1, 1.0f };
    gemm_mma_kernel<<<gg, 256, gemm_smem>>>(jk);
    GemmJob jv = { ahi + 2 * ASTRIDE, whi + 2 * WSTRIDE, bv, nullptr, vhi, 2, 1.0f };
    gemm_mma_kernel<<<gg, 256, gemm_smem>>>(jv);

    // 6. flash attention — writes O (hi) into activation set 0
    flash_mma_kernel<<<dim3(SEQ / 64, BH), 128, flash_smem>>>(
        qhi, khi, vhi, ahi);

    // 7. output projection — fp32 out
    GemmJob jo = { ahi, whi + 3 * WSTRIDE, bo, out, nullptr, 0, 1.0f };
    gemm_mma_kernel<<<gg, 256, gemm_smem>>>(jo);
}